// round 2
// baseline (speedup 1.0000x reference)
#include <cuda_runtime.h>

#define BATCH 64
#define SEQ   512
#define DIN   544
#define HID   1024
#define GATES 4096   // 4*HID

// ---------------- scratch (device globals: the sanctioned no-alloc path) ---
__device__ float g_xproj[(size_t)SEQ * BATCH * GATES];  // [S][B][4H], 512 MB
__device__ float g_h[2][BATCH * HID];
__device__ float g_c[BATCH * HID];

// ---------------- f32x2 packed-FMA helpers (Blackwell FFMA2) ---------------
static __device__ __forceinline__ unsigned long long pk2(float lo, float hi) {
    unsigned long long r;
    asm("mov.b64 %0, {%1, %2};" : "=l"(r) : "f"(lo), "f"(hi));
    return r;
}
static __device__ __forceinline__ void upk2(unsigned long long v, float& lo, float& hi) {
    asm("mov.b64 {%0, %1}, %2;" : "=f"(lo), "=f"(hi) : "l"(v));
}
static __device__ __forceinline__ unsigned long long ffma2(unsigned long long a,
                                                           unsigned long long b,
                                                           unsigned long long c) {
    unsigned long long d;
    asm("fma.rn.f32x2 %0, %1, %2, %3;" : "=l"(d) : "l"(a), "l"(b), "l"(c));
    return d;
}

static __device__ __forceinline__ float sigmoidf_(float x) {
    return 1.0f / (1.0f + __expf(-x));
}
static __device__ __forceinline__ float tanhf_(float x) {
    return 2.0f / (1.0f + __expf(-2.0f * x)) - 1.0f;
}

// ---------------- init: zero h0, c0 ---------------------------------------
__global__ void init_state() {
    int i = blockIdx.x * blockDim.x + threadIdx.x;
    if (i < BATCH * HID) {
        g_h[0][i] = 0.0f;
        g_c[i] = 0.0f;
    }
}

// ---------------- Phase 1: x_proj = X @ W_ih^T + (b_ih + b_hh) -------------
// GEMM M=32768 (m = b*SEQ + s), N=4096, K=544. NT (both K-major).
// 128x128 tile, BK=16, 256 threads, 8x8 micro-tile, FFMA2 over N pairs.
__global__ __launch_bounds__(256, 2) void xproj_gemm(
    const float* __restrict__ X, const float* __restrict__ Wih,
    const float* __restrict__ bih, const float* __restrict__ bhh)
{
    __shared__ float As[16][128];
    __shared__ float Bs[16][128];

    const int n0 = blockIdx.x * 128;
    const int m0 = blockIdx.y * 128;
    const int t  = threadIdx.x;
    const int tx = t & 15;       // 0..15  -> 8 cols
    const int ty = t >> 4;       // 0..15  -> 8 rows

    // load mapping: 2 float4 per thread per matrix
    const int lr = t >> 2;            // 0..63
    const int lc = (t & 3) << 2;      // 0,4,8,12

    const float* A0 = X   + (size_t)(m0 + lr) * DIN + lc;
    const float* A1 = X   + (size_t)(m0 + lr + 64) * DIN + lc;
    const float* B0 = Wih + (size_t)(n0 + lr) * DIN + lc;
    const float* B1 = Wih + (size_t)(n0 + lr + 64) * DIN + lc;

    unsigned long long acc[8][4];
#pragma unroll
    for (int i = 0; i < 8; ++i)
#pragma unroll
        for (int j = 0; j < 4; ++j) acc[i][j] = 0ULL;

    float4 pa0 = *(const float4*)(A0);
    float4 pa1 = *(const float4*)(A1);
    float4 pb0 = *(const float4*)(B0);
    float4 pb1 = *(const float4*)(B1);

    const int NKT = DIN / 16;  // 34
    for (int kt = 0; kt < NKT; ++kt) {
        As[lc + 0][lr]      = pa0.x; As[lc + 1][lr]      = pa0.y;
        As[lc + 2][lr]      = pa0.z; As[lc + 3][lr]      = pa0.w;
        As[lc + 0][lr + 64] = pa1.x; As[lc + 1][lr + 64] = pa1.y;
        As[lc + 2][lr + 64] = pa1.z; As[lc + 3][lr + 64] = pa1.w;
        Bs[lc + 0][lr]      = pb0.x; Bs[lc + 1][lr]      = pb0.y;
        Bs[lc + 2][lr]      = pb0.z; Bs[lc + 3][lr]      = pb0.w;
        Bs[lc + 0][lr + 64] = pb1.x; Bs[lc + 1][lr + 64] = pb1.y;
        Bs[lc + 2][lr + 64] = pb1.z; Bs[lc + 3][lr + 64] = pb1.w;
        __syncthreads();

        if (kt < NKT - 1) {
            int k0 = (kt + 1) * 16;
            pa0 = *(const float4*)(A0 + k0);
            pa1 = *(const float4*)(A1 + k0);
            pb0 = *(const float4*)(B0 + k0);
            pb1 = *(const float4*)(B1 + k0);
        }

#pragma unroll
        for (int k = 0; k < 16; ++k) {
            const float4 a0 = *(const float4*)&As[k][ty * 8];
            const float4 a1 = *(const float4*)&As[k][ty * 8 + 4];
            const unsigned long long* bp =
                (const unsigned long long*)&Bs[k][tx * 8];
            const unsigned long long b0 = bp[0], b1 = bp[1],
                                     b2 = bp[2], b3 = bp[3];
            const float av[8] = {a0.x, a0.y, a0.z, a0.w,
                                 a1.x, a1.y, a1.z, a1.w};
#pragma unroll
            for (int i = 0; i < 8; ++i) {
                unsigned long long av2 = pk2(av[i], av[i]);
                acc[i][0] = ffma2(av2, b0, acc[i][0]);
                acc[i][1] = ffma2(av2, b1, acc[i][1]);
                acc[i][2] = ffma2(av2, b2, acc[i][2]);
                acc[i][3] = ffma2(av2, b3, acc[i][3]);
            }
        }
        __syncthreads();
    }

    // bias pairs for my 8 columns
    float2 bias2[4];
#pragma unroll
    for (int jp = 0; jp < 4; ++jp) {
        int n = n0 + tx * 8 + jp * 2;
        bias2[jp] = make_float2(bih[n] + bhh[n], bih[n + 1] + bhh[n + 1]);
    }

#pragma unroll
    for (int i = 0; i < 8; ++i) {
        int m = m0 + ty * 8 + i;
        int b = m >> 9;       // m / SEQ
        int s = m & 511;      // m % SEQ
        float* orow = g_xproj + ((size_t)(s * BATCH + b)) * GATES + n0 + tx * 8;
#pragma unroll
        for (int jp = 0; jp < 4; ++jp) {
            float lo, hi;
            upk2(acc[i][jp], lo, hi);
            lo += bias2[jp].x;
            hi += bias2[jp].y;
            *(float2*)(orow + jp * 2) = make_float2(lo, hi);
        }
    }
}

// ---------------- Phase 2: one LSTM timestep -------------------------------
// Each block owns j-slice [j0, j0+8) across ALL FOUR gates (32 gate-cols),
// all 64 batch rows, full K=1024 — so the elementwise update fuses in.
// grid = 128 blocks, 256 threads. Thread: row m = tid&63, j-pair q = tid>>6.
__global__ __launch_bounds__(256) void lstm_step(const float* __restrict__ Whh, int t)
{
    __shared__ float hs[32][64];   // [k][batch-row]
    __shared__ float ws[32][32];   // [k][gate*8 + j]

    const float* __restrict__ h_in  = g_h[t & 1];
    float* __restrict__       h_out = g_h[(t & 1) ^ 1];
    const float* __restrict__ xp    = g_xproj + (size_t)t * (BATCH * GATES);

    const int j0  = blockIdx.x * 8;
    const int tid = threadIdx.x;
    const int m   = tid & 63;    // batch row
    const int q   = tid >> 6;    // 0..3 -> j pair (2q, 2q+1)

    // load mapping
    const int hr = tid >> 3;           // 0..31 (and +32)
    const int hc = (tid & 7) << 2;     // 0,4,...,28
    const int wcol = tid >> 3;         // 0..31 -> gate*8 + j
    const int wg = wcol >> 3;
    const int wj = wcol & 7;

    const float* hp0 = h_in + (size_t)hr * HID + hc;
    const float* hp1 = h_in + (size_t)(hr + 32) * HID + hc;
    const float* wp  = Whh + ((size_t)(wg * HID + j0 + wj)) * HID + hc;

    unsigned long long acc0 = 0, acc1 = 0, acc2 = 0, acc3 = 0;

    float4 ph0 = *(const float4*)(hp0);
    float4 ph1 = *(const float4*)(hp1);
    float4 pw  = *(const float4*)(wp);

    for (int kt = 0; kt < 32; ++kt) {
        hs[hc + 0][hr]      = ph0.x; hs[hc + 1][hr]      = ph0.y;
        hs[hc + 2][hr]      = ph0.z; hs[hc + 3][hr]      = ph0.w;
        hs[hc + 0][hr + 32] = ph1.x; hs[hc + 1][hr + 32] = ph1.y;
        hs[hc + 2][hr + 32] = ph1.z; hs[hc + 3][hr + 32] = ph1.w;
        ws[hc + 0][wcol] = pw.x; ws[hc + 1][wcol] = pw.y;
        ws[hc + 2][wcol] = pw.z; ws[hc + 3][wcol] = pw.w;
        __syncthreads();

        if (kt < 31) {
            int k0 = (kt + 1) * 32;
            ph0 = *(const float4*)(hp0 + k0);
            ph1 = *(const float4*)(hp1 + k0);
            pw  = *(const float4*)(wp + k0);
        }

#pragma unroll
        for (int k = 0; k < 32; ++k) {
            float a = hs[k][m];
            unsigned long long av = pk2(a, a);
            const unsigned long long* bp = (const unsigned long long*)&ws[k][0];
            acc0 = ffma2(av, bp[q],      acc0);
            acc1 = ffma2(av, bp[4 + q],  acc1);
            acc2 = ffma2(av, bp[8 + q],  acc2);
            acc3 = ffma2(av, bp[12 + q], acc3);
        }
        __syncthreads();
    }

    // ---- fused LSTM elementwise epilogue ----
    const int j = j0 + 2 * q;
    const float2* xr = (const float2*)(xp + (size_t)m * GATES);
    float2 xi = xr[(0 * HID + j) >> 1];
    float2 xf = xr[(1 * HID + j) >> 1];
    float2 xg = xr[(2 * HID + j) >> 1];
    float2 xo = xr[(3 * HID + j) >> 1];

    float i_lo, i_hi, f_lo, f_hi, gg_lo, gg_hi, o_lo, o_hi;
    upk2(acc0, i_lo, i_hi);
    upk2(acc1, f_lo, f_hi);
    upk2(acc2, gg_lo, gg_hi);
    upk2(acc3, o_lo, o_hi);
    i_lo += xi.x;  i_hi += xi.y;
    f_lo += xf.x;  f_hi += xf.y;
    gg_lo += xg.x; gg_hi += xg.y;
    o_lo += xo.x;  o_hi += xo.y;

    float2* cp = (float2*)(g_c + (size_t)m * HID + j);
    float2 cv = *cp;
    float c0 = sigmoidf_(f_lo) * cv.x + sigmoidf_(i_lo) * tanhf_(gg_lo);
    float c1 = sigmoidf_(f_hi) * cv.y + sigmoidf_(i_hi) * tanhf_(gg_hi);
    *cp = make_float2(c0, c1);

    float2* hp = (float2*)(h_out + (size_t)m * HID + j);
    *hp = make_float2(sigmoidf_(o_lo) * tanhf_(c0),
                      sigmoidf_(o_hi) * tanhf_(c1));
}

// ---------------- copy final state to output -------------------------------
// t goes 0..511; final h ends up in g_h[0] (512 flips from g_h[0]).
__global__ void copy_out(float* __restrict__ out) {
    int i = blockIdx.x * blockDim.x + threadIdx.x;
    if (i < BATCH * HID) {
        out[i] = g_h[0][i];
    } else if (i < 2 * BATCH * HID) {
        out[i] = g_c[i - BATCH * HID];
    }
}

// ---------------- launch ---------------------------------------------------
extern "C" void kernel_launch(void* const* d_in, const int* in_sizes, int n_in,
                              void* d_out, int out_size) {
    const float* X   = (const float*)d_in[0];
    const float* Wih = (const float*)d_in[1];
    const float* Whh = (const float*)d_in[2];
    const float* bih = (const float*)d_in[3];
    const float* bhh = (const float*)d_in[4];
    float* out = (float*)d_out;

    init_state<<<256, 256>>>();
    xproj_gemm<<<dim3(GATES / 128, (BATCH * SEQ) / 128), 256>>>(X, Wih, bih, bhh);
    for (int t = 0; t < SEQ; ++t) {
        lstm_step<<<128, 256>>>(Whh, t);
    }
    copy_out<<<512, 256>>>(out);
}

// round 3
// speedup vs baseline: 1.0012x; 1.0012x over previous
#include <cuda_runtime.h>

#define BATCH 64
#define SEQ   512
#define DIN   544
#define HID   1024
#define GATES 4096   // 4*HID

// ---------------- scratch (device globals: the sanctioned no-alloc path) ---
__device__ float g_xproj[(size_t)SEQ * BATCH * GATES];  // [S][B][4H], 512 MB
__device__ float g_h[2][BATCH * HID];
__device__ float g_c[BATCH * HID];

// ---------------- f32x2 packed-FMA helpers (Blackwell FFMA2) ---------------
static __device__ __forceinline__ unsigned long long pk2(float lo, float hi) {
    unsigned long long r;
    asm("mov.b64 %0, {%1, %2};" : "=l"(r) : "f"(lo), "f"(hi));
    return r;
}
static __device__ __forceinline__ void upk2(unsigned long long v, float& lo, float& hi) {
    asm("mov.b64 {%0, %1}, %2;" : "=f"(lo), "=f"(hi) : "l"(v));
}
static __device__ __forceinline__ unsigned long long ffma2(unsigned long long a,
                                                           unsigned long long b,
                                                           unsigned long long c) {
    unsigned long long d;
    asm("fma.rn.f32x2 %0, %1, %2, %3;" : "=l"(d) : "l"(a), "l"(b), "l"(c));
    return d;
}

static __device__ __forceinline__ float sigmoidf_(float x) {
    return 1.0f / (1.0f + __expf(-x));
}
static __device__ __forceinline__ float tanhf_(float x) {
    return 2.0f / (1.0f + __expf(-2.0f * x)) - 1.0f;
}

// ---------------- init: zero h0, c0 ---------------------------------------
__global__ void init_state() {
    int i = blockIdx.x * blockDim.x + threadIdx.x;
    if (i < BATCH * HID) {
        g_h[0][i] = 0.0f;
        g_c[i] = 0.0f;
    }
}

// ---------------- Phase 1: x_proj = X @ W_ih^T + (b_ih + b_hh) -------------
// GEMM M=32768 (m = b*SEQ + s), N=4096, K=544. NT (both K-major).
// 128x128 tile, BK=16, 256 threads, 8x8 micro-tile, FFMA2 over N pairs.
__global__ __launch_bounds__(256, 2) void xproj_gemm(
    const float* __restrict__ X, const float* __restrict__ Wih,
    const float* __restrict__ bih, const float* __restrict__ bhh)
{
    __shared__ float As[16][128];
    __shared__ float Bs[16][128];

    const int n0 = blockIdx.x * 128;
    const int m0 = blockIdx.y * 128;
    const int t  = threadIdx.x;
    const int tx = t & 15;       // 0..15  -> 8 cols
    const int ty = t >> 4;       // 0..15  -> 8 rows

    // load mapping: 2 float4 per thread per matrix
    const int lr = t >> 2;            // 0..63
    const int lc = (t & 3) << 2;      // 0,4,8,12

    const float* A0 = X   + (size_t)(m0 + lr) * DIN + lc;
    const float* A1 = X   + (size_t)(m0 + lr + 64) * DIN + lc;
    const float* B0 = Wih + (size_t)(n0 + lr) * DIN + lc;
    const float* B1 = Wih + (size_t)(n0 + lr + 64) * DIN + lc;

    unsigned long long acc[8][4];
#pragma unroll
    for (int i = 0; i < 8; ++i)
#pragma unroll
        for (int j = 0; j < 4; ++j) acc[i][j] = 0ULL;

    float4 pa0 = *(const float4*)(A0);
    float4 pa1 = *(const float4*)(A1);
    float4 pb0 = *(const float4*)(B0);
    float4 pb1 = *(const float4*)(B1);

    const int NKT = DIN / 16;  // 34
    for (int kt = 0; kt < NKT; ++kt) {
        As[lc + 0][lr]      = pa0.x; As[lc + 1][lr]      = pa0.y;
        As[lc + 2][lr]      = pa0.z; As[lc + 3][lr]      = pa0.w;
        As[lc + 0][lr + 64] = pa1.x; As[lc + 1][lr + 64] = pa1.y;
        As[lc + 2][lr + 64] = pa1.z; As[lc + 3][lr + 64] = pa1.w;
        Bs[lc + 0][lr]      = pb0.x; Bs[lc + 1][lr]      = pb0.y;
        Bs[lc + 2][lr]      = pb0.z; Bs[lc + 3][lr]      = pb0.w;
        Bs[lc + 0][lr + 64] = pb1.x; Bs[lc + 1][lr + 64] = pb1.y;
        Bs[lc + 2][lr + 64] = pb1.z; Bs[lc + 3][lr + 64] = pb1.w;
        __syncthreads();

        if (kt < NKT - 1) {
            int k0 = (kt + 1) * 16;
            pa0 = *(const float4*)(A0 + k0);
            pa1 = *(const float4*)(A1 + k0);
            pb0 = *(const float4*)(B0 + k0);
            pb1 = *(const float4*)(B1 + k0);
        }

#pragma unroll
        for (int k = 0; k < 16; ++k) {
            const float4 a0 = *(const float4*)&As[k][ty * 8];
            const float4 a1 = *(const float4*)&As[k][ty * 8 + 4];
            const unsigned long long* bp =
                (const unsigned long long*)&Bs[k][tx * 8];
            const unsigned long long b0 = bp[0], b1 = bp[1],
                                     b2 = bp[2], b3 = bp[3];
            const float av[8] = {a0.x, a0.y, a0.z, a0.w,
                                 a1.x, a1.y, a1.z, a1.w};
#pragma unroll
            for (int i = 0; i < 8; ++i) {
                unsigned long long av2 = pk2(av[i], av[i]);
                acc[i][0] = ffma2(av2, b0, acc[i][0]);
                acc[i][1] = ffma2(av2, b1, acc[i][1]);
                acc[i][2] = ffma2(av2, b2, acc[i][2]);
                acc[i][3] = ffma2(av2, b3, acc[i][3]);
            }
        }
        __syncthreads();
    }

    // bias pairs for my 8 columns
    float2 bias2[4];
#pragma unroll
    for (int jp = 0; jp < 4; ++jp) {
        int n = n0 + tx * 8 + jp * 2;
        bias2[jp] = make_float2(bih[n] + bhh[n], bih[n + 1] + bhh[n + 1]);
    }

#pragma unroll
    for (int i = 0; i < 8; ++i) {
        int m = m0 + ty * 8 + i;
        int b = m >> 9;       // m / SEQ
        int s = m & 511;      // m % SEQ
        float* orow = g_xproj + ((size_t)(s * BATCH + b)) * GATES + n0 + tx * 8;
#pragma unroll
        for (int jp = 0; jp < 4; ++jp) {
            float lo, hi;
            upk2(acc[i][jp], lo, hi);
            lo += bias2[jp].x;
            hi += bias2[jp].y;
            *(float2*)(orow + jp * 2) = make_float2(lo, hi);
        }
    }
}

// ---------------- Phase 2: one LSTM timestep -------------------------------
// Each block owns j-slice [j0, j0+8) across ALL FOUR gates (32 gate-cols),
// all 64 batch rows, full K=1024 — so the elementwise update fuses in.
// grid = 128 blocks, 256 threads. Thread: row m = tid&63, j-pair q = tid>>6.
__global__ __launch_bounds__(256) void lstm_step(const float* __restrict__ Whh, int t)
{
    __shared__ float hs[32][64];   // [k][batch-row]
    __shared__ float ws[32][32];   // [k][gate*8 + j]

    const float* __restrict__ h_in  = g_h[t & 1];
    float* __restrict__       h_out = g_h[(t & 1) ^ 1];
    const float* __restrict__ xp    = g_xproj + (size_t)t * (BATCH * GATES);

    const int j0  = blockIdx.x * 8;
    const int tid = threadIdx.x;
    const int m   = tid & 63;    // batch row
    const int q   = tid >> 6;    // 0..3 -> j pair (2q, 2q+1)

    // load mapping
    const int hr = tid >> 3;           // 0..31 (and +32)
    const int hc = (tid & 7) << 2;     // 0,4,...,28
    const int wcol = tid >> 3;         // 0..31 -> gate*8 + j
    const int wg = wcol >> 3;
    const int wj = wcol & 7;

    const float* hp0 = h_in + (size_t)hr * HID + hc;
    const float* hp1 = h_in + (size_t)(hr + 32) * HID + hc;
    const float* wp  = Whh + ((size_t)(wg * HID + j0 + wj)) * HID + hc;

    unsigned long long acc0 = 0, acc1 = 0, acc2 = 0, acc3 = 0;

    float4 ph0 = *(const float4*)(hp0);
    float4 ph1 = *(const float4*)(hp1);
    float4 pw  = *(const float4*)(wp);

    for (int kt = 0; kt < 32; ++kt) {
        hs[hc + 0][hr]      = ph0.x; hs[hc + 1][hr]      = ph0.y;
        hs[hc + 2][hr]      = ph0.z; hs[hc + 3][hr]      = ph0.w;
        hs[hc + 0][hr + 32] = ph1.x; hs[hc + 1][hr + 32] = ph1.y;
        hs[hc + 2][hr + 32] = ph1.z; hs[hc + 3][hr + 32] = ph1.w;
        ws[hc + 0][wcol] = pw.x; ws[hc + 1][wcol] = pw.y;
        ws[hc + 2][wcol] = pw.z; ws[hc + 3][wcol] = pw.w;
        __syncthreads();

        if (kt < 31) {
            int k0 = (kt + 1) * 32;
            ph0 = *(const float4*)(hp0 + k0);
            ph1 = *(const float4*)(hp1 + k0);
            pw  = *(const float4*)(wp + k0);
        }

#pragma unroll
        for (int k = 0; k < 32; ++k) {
            float a = hs[k][m];
            unsigned long long av = pk2(a, a);
            const unsigned long long* bp = (const unsigned long long*)&ws[k][0];
            acc0 = ffma2(av, bp[q],      acc0);
            acc1 = ffma2(av, bp[4 + q],  acc1);
            acc2 = ffma2(av, bp[8 + q],  acc2);
            acc3 = ffma2(av, bp[12 + q], acc3);
        }
        __syncthreads();
    }

    // ---- fused LSTM elementwise epilogue ----
    const int j = j0 + 2 * q;
    const float2* xr = (const float2*)(xp + (size_t)m * GATES);
    float2 xi = xr[(0 * HID + j) >> 1];
    float2 xf = xr[(1 * HID + j) >> 1];
    float2 xg = xr[(2 * HID + j) >> 1];
    float2 xo = xr[(3 * HID + j) >> 1];

    float i_lo, i_hi, f_lo, f_hi, gg_lo, gg_hi, o_lo, o_hi;
    upk2(acc0, i_lo, i_hi);
    upk2(acc1, f_lo, f_hi);
    upk2(acc2, gg_lo, gg_hi);
    upk2(acc3, o_lo, o_hi);
    i_lo += xi.x;  i_hi += xi.y;
    f_lo += xf.x;  f_hi += xf.y;
    gg_lo += xg.x; gg_hi += xg.y;
    o_lo += xo.x;  o_hi += xo.y;

    float2* cp = (float2*)(g_c + (size_t)m * HID + j);
    float2 cv = *cp;
    float c0 = sigmoidf_(f_lo) * cv.x + sigmoidf_(i_lo) * tanhf_(gg_lo);
    float c1 = sigmoidf_(f_hi) * cv.y + sigmoidf_(i_hi) * tanhf_(gg_hi);
    *cp = make_float2(c0, c1);

    float2* hp = (float2*)(h_out + (size_t)m * HID + j);
    *hp = make_float2(sigmoidf_(o_lo) * tanhf_(c0),
                      sigmoidf_(o_hi) * tanhf_(c1));
}

// ---------------- copy final state to output -------------------------------
// t goes 0..511; final h ends up in g_h[0] (512 flips from g_h[0]).
__global__ void copy_out(float* __restrict__ out) {
    int i = blockIdx.x * blockDim.x + threadIdx.x;
    if (i < BATCH * HID) {
        out[i] = g_h[0][i];
    } else if (i < 2 * BATCH * HID) {
        out[i] = g_c[i - BATCH * HID];
    }
}

// ---------------- launch ---------------------------------------------------
extern "C" void kernel_launch(void* const* d_in, const int* in_sizes, int n_in,
                              void* d_out, int out_size) {
    const float* X   = (const float*)d_in[0];
    const float* Wih = (const float*)d_in[1];
    const float* Whh = (const float*)d_in[2];
    const float* bih = (const float*)d_in[3];
    const float* bhh = (const float*)d_in[4];
    float* out = (float*)d_out;

    init_state<<<256, 256>>>();
    xproj_gemm<<<dim3(GATES / 128, (BATCH * SEQ) / 128), 256>>>(X, Wih, bih, bhh);
    for (int t = 0; t < SEQ; ++t) {
        lstm_step<<<128, 256>>>(Whh, t);
    }
    copy_out<<<512, 256>>>(out);
}

// round 5
// speedup vs baseline: 3.2211x; 3.2173x over previous
#include <cuda_runtime.h>
#include <cuda_bf16.h>
#include <cstdint>

#define BATCH 64
#define SEQ   512
#define DIN   544
#define HID   1024
#define GATES 4096
#define NCTA  128

// ---------------- device-global scratch ------------------------------------
__device__ float          g_xproj[(size_t)SEQ * BATCH * GATES];   // [s][b][4H]
__device__ __nv_bfloat16  g_w2[(size_t)GATES * 2048];             // row r=4j+g: [Whi(1024)|Wlo(1024)]
__device__ __nv_bfloat16  g_hcat[2][(size_t)BATCH * 2048];        // [m][hhi(1024)|hlo(1024)]
__device__ unsigned       g_bar_count;
__device__ unsigned       g_bar_gen;

// ---------------- helpers ---------------------------------------------------
static __device__ __forceinline__ unsigned long long pk2(float lo, float hi) {
    unsigned long long r;
    asm("mov.b64 %0, {%1, %2};" : "=l"(r) : "f"(lo), "f"(hi));
    return r;
}
static __device__ __forceinline__ void upk2(unsigned long long v, float& lo, float& hi) {
    asm("mov.b64 {%0, %1}, %2;" : "=f"(lo), "=f"(hi) : "l"(v));
}
static __device__ __forceinline__ unsigned long long ffma2(unsigned long long a,
                                                           unsigned long long b,
                                                           unsigned long long c) {
    unsigned long long d;
    asm("fma.rn.f32x2 %0, %1, %2, %3;" : "=l"(d) : "l"(a), "l"(b), "l"(c));
    return d;
}
static __device__ __forceinline__ uint32_t smem_u32(const void* p) {
    uint32_t a;
    asm("{ .reg .u64 t; cvta.to.shared.u64 t, %1; cvt.u32.u64 %0, t; }" : "=r"(a) : "l"(p));
    return a;
}
static __device__ __forceinline__ void cp16(uint32_t dst, const void* src) {
    asm volatile("cp.async.cg.shared.global [%0], [%1], 16;" :: "r"(dst), "l"(src) : "memory");
}
#define CP_COMMIT() asm volatile("cp.async.commit_group;" ::: "memory")
#define CP_WAIT1()  asm volatile("cp.async.wait_group 1;" ::: "memory")
#define CP_WAIT0()  asm volatile("cp.async.wait_group 0;" ::: "memory")

#define LDSM4(r0, r1, r2, r3, addr) \
    asm volatile("ldmatrix.sync.aligned.m8n8.x4.shared.b16 {%0,%1,%2,%3}, [%4];" \
        : "=r"(r0), "=r"(r1), "=r"(r2), "=r"(r3) : "r"(addr))

#define MMA16816(c, a0, a1, a2, a3, b0, b1) \
    asm volatile("mma.sync.aligned.m16n8k16.row.col.f32.bf16.bf16.f32 " \
        "{%0,%1,%2,%3}, {%4,%5,%6,%7}, {%8,%9}, {%0,%1,%2,%3};" \
        : "+f"((c)[0]), "+f"((c)[1]), "+f"((c)[2]), "+f"((c)[3]) \
        : "r"(a0), "r"(a1), "r"(a2), "r"(a3), "r"(b0), "r"(b1))

static __device__ __forceinline__ float sigmoidf_(float x) {
    return 1.0f / (1.0f + __expf(-x));
}
static __device__ __forceinline__ float tanhf_(float x) {
    return 2.0f / (1.0f + __expf(-2.0f * x)) - 1.0f;
}

// ---------------- init ------------------------------------------------------
__global__ void init_state() {
    int i = blockIdx.x * blockDim.x + threadIdx.x;
    if (i < BATCH * 2048) g_hcat[0][i] = __float2bfloat16(0.0f);
    if (i == 0) { g_bar_count = 0u; g_bar_gen = 0u; }
}

// row r = 4j+g  <-  W_hh row g*HID + j ; cols: [hi(1024) | lo(1024)]
__global__ void wsplit(const float* __restrict__ W) {
    size_t idx = (size_t)blockIdx.x * 256 + threadIdx.x;
    if (idx >= (size_t)GATES * HID) return;
    int r = (int)(idx >> 10), k = (int)(idx & 1023);
    int j = r >> 2, g = r & 3;
    float v = W[(size_t)(g * HID + j) * HID + k];
    __nv_bfloat16 hi = __float2bfloat16(v);
    __nv_bfloat16 lo = __float2bfloat16(v - __bfloat162float(hi));
    __nv_bfloat16* o = g_w2 + (size_t)r * 2048;
    o[k] = hi; o[1024 + k] = lo;
}

// ---------------- Phase 1: x_proj fp32 GEMM (FFMA2, unchanged/passing) -----
__global__ __launch_bounds__(256, 2) void xproj_gemm(
    const float* __restrict__ X, const float* __restrict__ Wih,
    const float* __restrict__ bih, const float* __restrict__ bhh)
{
    __shared__ float As[16][128];
    __shared__ float Bs[16][128];
    const int n0 = blockIdx.x * 128, m0 = blockIdx.y * 128;
    const int t = threadIdx.x, tx = t & 15, ty = t >> 4;
    const int lr = t >> 2, lc = (t & 3) << 2;

    const float* A0 = X   + (size_t)(m0 + lr) * DIN + lc;
    const float* A1 = X   + (size_t)(m0 + lr + 64) * DIN + lc;
    const float* B0 = Wih + (size_t)(n0 + lr) * DIN + lc;
    const float* B1 = Wih + (size_t)(n0 + lr + 64) * DIN + lc;

    unsigned long long acc[8][4];
#pragma unroll
    for (int i = 0; i < 8; ++i)
#pragma unroll
        for (int j = 0; j < 4; ++j) acc[i][j] = 0ULL;

    float4 pa0 = *(const float4*)A0, pa1 = *(const float4*)A1;
    float4 pb0 = *(const float4*)B0, pb1 = *(const float4*)B1;

    const int NKT = DIN / 16;
    for (int kt = 0; kt < NKT; ++kt) {
        As[lc+0][lr] = pa0.x; As[lc+1][lr] = pa0.y; As[lc+2][lr] = pa0.z; As[lc+3][lr] = pa0.w;
        As[lc+0][lr+64] = pa1.x; As[lc+1][lr+64] = pa1.y; As[lc+2][lr+64] = pa1.z; As[lc+3][lr+64] = pa1.w;
        Bs[lc+0][lr] = pb0.x; Bs[lc+1][lr] = pb0.y; Bs[lc+2][lr] = pb0.z; Bs[lc+3][lr] = pb0.w;
        Bs[lc+0][lr+64] = pb1.x; Bs[lc+1][lr+64] = pb1.y; Bs[lc+2][lr+64] = pb1.z; Bs[lc+3][lr+64] = pb1.w;
        __syncthreads();
        if (kt < NKT - 1) {
            int k0 = (kt + 1) * 16;
            pa0 = *(const float4*)(A0 + k0); pa1 = *(const float4*)(A1 + k0);
            pb0 = *(const float4*)(B0 + k0); pb1 = *(const float4*)(B1 + k0);
        }
#pragma unroll
        for (int k = 0; k < 16; ++k) {
            const float4 a0 = *(const float4*)&As[k][ty * 8];
            const float4 a1 = *(const float4*)&As[k][ty * 8 + 4];
            const unsigned long long* bp = (const unsigned long long*)&Bs[k][tx * 8];
            const unsigned long long b0 = bp[0], b1 = bp[1], b2 = bp[2], b3 = bp[3];
            const float av[8] = {a0.x, a0.y, a0.z, a0.w, a1.x, a1.y, a1.z, a1.w};
#pragma unroll
            for (int i = 0; i < 8; ++i) {
                unsigned long long a2 = pk2(av[i], av[i]);
                acc[i][0] = ffma2(a2, b0, acc[i][0]);
                acc[i][1] = ffma2(a2, b1, acc[i][1]);
                acc[i][2] = ffma2(a2, b2, acc[i][2]);
                acc[i][3] = ffma2(a2, b3, acc[i][3]);
            }
        }
        __syncthreads();
    }

    float2 bias2[4];
#pragma unroll
    for (int jp = 0; jp < 4; ++jp) {
        int n = n0 + tx * 8 + jp * 2;
        bias2[jp] = make_float2(bih[n] + bhh[n], bih[n + 1] + bhh[n + 1]);
    }
#pragma unroll
    for (int i = 0; i < 8; ++i) {
        int m = m0 + ty * 8 + i;
        int b = m >> 9, s = m & 511;
        float* orow = g_xproj + ((size_t)(s * BATCH + b)) * GATES + n0 + tx * 8;
#pragma unroll
        for (int jp = 0; jp < 4; ++jp) {
            float lo, hi; upk2(acc[i][jp], lo, hi);
            *(float2*)(orow + jp * 2) = make_float2(lo + bias2[jp].x, hi + bias2[jp].y);
        }
    }
}

// ---------------- Phase 2: persistent HMMA LSTM ----------------------------
// smem layout (dynamic):
//   [0, 131072)            W: Whi region [32 rows x 2048B] + Wlo region
//   [131072, 180224)       h ring: 3 x 16384 (chunk = 64 n x 256B)
//   [180224, 188544)       staging st[32][65] fp32
//   [188544, 190592)       c slice [64 m][8 j] fp32
#define SM_W    0
#define SM_RING 131072
#define SM_ST   180224
#define SM_CS   188544
#define SMEM_DYN 190592

__device__ __forceinline__ void grid_barrier(unsigned target) {
    __syncthreads();
    if (threadIdx.x == 0) {
        __threadfence();
        unsigned arr = atomicAdd(&g_bar_count, 1u);
        if (arr == NCTA - 1u) {
            g_bar_count = 0u;
            __threadfence();
            atomicAdd(&g_bar_gen, 1u);
        } else {
            unsigned g;
            do {
                asm volatile("ld.acquire.gpu.global.u32 %0, [%1];"
                             : "=r"(g) : "l"(&g_bar_gen));
            } while (g < target);
        }
        __threadfence();
    }
    __syncthreads();
}

__global__ __launch_bounds__(256, 1) void lstm_persistent(float* __restrict__ out) {
    extern __shared__ char smem[];
    const uint32_t sb = smem_u32(smem);
    const int tid = threadIdx.x, wid = tid >> 5, lane = tid & 31;
    const int rbase = blockIdx.x * 32;    // reordered W rows
    const int jbase = blockIdx.x * 8;     // hidden cols

    float (*st)[65] = (float (*)[65])(smem + SM_ST);
    float* cs = (float*)(smem + SM_CS);

    // ---- load W slice into smem once (128 KB) ----
#pragma unroll 8
    for (int w = 0; w < 32; ++w) {
        int v = tid + 256 * w;            // 0..8191
        int row = v >> 8, u = v & 255;
        int reg = u >> 7, uu = u & 127;
        uint32_t dst = sb + SM_W + reg * 65536 + row * 2048
                     + (((uu) & ~7) | ((uu ^ row) & 7)) * 16;
        cp16(dst, g_w2 + (size_t)(rbase + row) * 2048 + u * 8);
    }
    CP_COMMIT();
    // zero c slice
    cs[tid] = 0.0f; cs[tid + 256] = 0.0f;
    CP_WAIT0();
    __syncthreads();

    // per-warp invariants
    const int mi = wid & 1, ni = wid >> 1;
    const int lrow = lane & 15, lk = lane >> 4;
    const int arow = 16 * mi + lrow;
    const int brow = 16 * ni + lrow;
    const uint32_t aHi = sb + SM_W + arow * 2048;
    const uint32_t aLo = aHi + 65536;
    const uint32_t bRow0 = sb + SM_RING + brow * 256;

    // epilogue mapping
    const int ejl = tid & 7, emh = tid >> 3;   // j lane, m group

    for (int t = 0; t < SEQ; ++t) {
        const __nv_bfloat16* __restrict__ hin = g_hcat[t & 1];
        __nv_bfloat16* __restrict__ hout = g_hcat[(t & 1) ^ 1];
        const float* __restrict__ xp = g_xproj + (size_t)t * BATCH * GATES;

        float ca[4] = {0.f, 0.f, 0.f, 0.f};
        float cb[4] = {0.f, 0.f, 0.f, 0.f};

        // issue h chunk j (j even: hhi[j/2], odd: hlo[j/2]) into ring buf j%3
        auto issue_h = [&](int j) {
            const int q = j >> 1;
            const int koff = ((j & 1) ? 1024 : 0) + q * 128;
            const uint32_t dst0 = sb + SM_RING + (j % 3) * 16384;
#pragma unroll
            for (int w = 0; w < 4; ++w) {
                int v = tid + 256 * w;        // 0..1023
                int n = v >> 4, u = v & 15;
                uint32_t dst = dst0 + n * 256 + ((u & ~7) | ((u ^ n) & 7)) * 16;
                cp16(dst, hin + (size_t)n * 2048 + koff + u * 8);
            }
            CP_COMMIT();
        };

        auto consume = [&](uint32_t aBase, int koA, uint32_t bBase) {
#pragma unroll
            for (int ks = 0; ks < 8; ++ks) {
                int ua = koA * 16 + 2 * ks + lk;
                uint32_t aaddr = aBase + ((ua & ~7) | ((ua ^ arow) & 7)) * 16;
                int ub = 2 * ks + lk;
                uint32_t baddr = bBase + ((ub & ~7) | ((ub ^ brow) & 7)) * 16;
                uint32_t a0, a1, a2, a3, b0, b1, b2, b3;
                LDSM4(a0, a1, a2, a3, aaddr);
                LDSM4(b0, b1, b2, b3, baddr);
                MMA16816(ca, a0, a1, a2, a3, b0, b2);
                MMA16816(cb, a0, a1, a2, a3, b1, b3);
            }
        };

        issue_h(0);
        issue_h(1);

#pragma unroll 1
        for (int q = 0; q < 8; ++q) {
            // event: wait load 2q, issue load 2q+2
            {
                const int li = 2 * q;
                if (li < 15) { CP_WAIT1(); } else { CP_WAIT0(); }
                __syncthreads();
                if (li + 2 <= 15) issue_h(li + 2);
            }
            const uint32_t bHi = bRow0 + ((2 * q) % 3) * 16384;
            consume(aHi, q, bHi);     // Whi @ hhi_q
            consume(aLo, q, bHi);     // Wlo @ hhi_q
            // event: wait load 2q+1, issue load 2q+3
            {
                const int li = 2 * q + 1;
                if (li < 15) { CP_WAIT1(); } else { CP_WAIT0(); }
                __syncthreads();
                if (li + 2 <= 15) issue_h(li + 2);
            }
            const uint32_t bLoB = bRow0 + ((2 * q + 1) % 3) * 16384;
            consume(aHi, q, bLoB);    // Whi @ hlo_q
        }

        // ---- stage C frags ----
        {
            const int gid = lane >> 2, tig = lane & 3;
            const int r0 = 16 * mi + gid;
            const int c0 = 16 * ni + 2 * tig;
            st[r0][c0]         = ca[0]; st[r0][c0 + 1]     = ca[1];
            st[r0 + 8][c0]     = ca[2]; st[r0 + 8][c0 + 1] = ca[3];
            st[r0][c0 + 8]     = cb[0]; st[r0][c0 + 9]     = cb[1];
            st[r0 + 8][c0 + 8] = cb[2]; st[r0 + 8][c0 + 9] = cb[3];
        }
        __syncthreads();

        // ---- fused LSTM elementwise epilogue ----
#pragma unroll
        for (int pass = 0; pass < 2; ++pass) {
            const int m = emh + pass * 32;
            const float* xr = xp + (size_t)m * GATES;
            const int j = jbase + ejl;
            float gi = st[ejl * 4 + 0][m] + xr[j];
            float gf = st[ejl * 4 + 1][m] + xr[HID + j];
            float gg = st[ejl * 4 + 2][m] + xr[2 * HID + j];
            float go = st[ejl * 4 + 3][m] + xr[3 * HID + j];
            float cold = cs[m * 8 + ejl];
            float cn = sigmoidf_(gf) * cold + sigmoidf_(gi) * tanhf_(gg);
            cs[m * 8 + ejl] = cn;
            float h = sigmoidf_(go) * tanhf_(cn);
            __nv_bfloat16 hi = __float2bfloat16(h);
            __nv_bfloat16 lo = __float2bfloat16(h - __bfloat162float(hi));
            hout[(size_t)m * 2048 + j] = hi;
            hout[(size_t)m * 2048 + 1024 + j] = lo;
            if (t == SEQ - 1) {
                out[(size_t)m * HID + j] = h;
                out[(size_t)BATCH * HID + (size_t)m * HID + j] = cn;
            }
        }

        if (t < SEQ - 1) grid_barrier((unsigned)(t + 1));
    }
}

// ---------------- launch ---------------------------------------------------
extern "C" void kernel_launch(void* const* d_in, const int* in_sizes, int n_in,
                              void* d_out, int out_size) {
    const float* X   = (const float*)d_in[0];
    const float* Wih = (const float*)d_in[1];
    const float* Whh = (const float*)d_in[2];
    const float* bih = (const float*)d_in[3];
    const float* bhh = (const float*)d_in[4];
    float* out = (float*)d_out;

    static int configured = 0;
    if (!configured) {
        cudaFuncSetAttribute(lstm_persistent,
                             cudaFuncAttributeMaxDynamicSharedMemorySize, SMEM_DYN);
        configured = 1;
    }

    init_state<<<512, 256>>>();
    wsplit<<<(GATES * HID) / 256, 256>>>(Whh);
    xproj_gemm<<<dim3(GATES / 128, (BATCH * SEQ) / 128), 256>>>(X, Wih, bih, bhh);
    lstm_persistent<<<NCTA, 256, SMEM_DYN>>>(out);
}

// round 7
// speedup vs baseline: 4.2739x; 1.3268x over previous
#include <cuda_runtime.h>
#include <cuda_bf16.h>
#include <cstdint>

#define BATCH 64
#define SEQ   512
#define DIN   544
#define HID   1024
#define GATES 4096
#define NCTA  128
#define KX    1632   // 3*544 split-K for xproj

// ---------------- device-global scratch ------------------------------------
__device__ float          g_xproj[(size_t)SEQ * BATCH * GATES];   // [s][b][4H]
__device__ __nv_bfloat16  g_w2[(size_t)GATES * 2048];             // r=4j+g: [Whi|Wlo]
__device__ __nv_bfloat16  g_hcat[2][(size_t)BATCH * 2048];        // [m][hhi|hlo]
__device__ __nv_bfloat16  g_xs[(size_t)BATCH * SEQ * KX];         // [m][Xhi|Xlo|Xhi]
__device__ __nv_bfloat16  g_ws[(size_t)GATES * KX];               // [n][Whi|Whi|Wlo]
__device__ unsigned       g_bar_count;
__device__ unsigned       g_bar_gen;

// ---------------- helpers ---------------------------------------------------
static __device__ __forceinline__ uint32_t smem_u32(const void* p) {
    uint32_t a;
    asm("{ .reg .u64 t; cvta.to.shared.u64 t, %1; cvt.u32.u64 %0, t; }" : "=r"(a) : "l"(p));
    return a;
}
static __device__ __forceinline__ void cp16(uint32_t dst, const void* src) {
    asm volatile("cp.async.cg.shared.global [%0], [%1], 16;" :: "r"(dst), "l"(src) : "memory");
}
#define CP_COMMIT() asm volatile("cp.async.commit_group;" ::: "memory")
#define CP_WAIT1()  asm volatile("cp.async.wait_group 1;" ::: "memory")
#define CP_WAIT0()  asm volatile("cp.async.wait_group 0;" ::: "memory")

#define LDSM4(r0, r1, r2, r3, addr) \
    asm volatile("ldmatrix.sync.aligned.m8n8.x4.shared.b16 {%0,%1,%2,%3}, [%4];" \
        : "=r"(r0), "=r"(r1), "=r"(r2), "=r"(r3) : "r"(addr))

#define MMA16816(c, a0, a1, a2, a3, b0, b1) \
    asm volatile("mma.sync.aligned.m16n8k16.row.col.f32.bf16.bf16.f32 " \
        "{%0,%1,%2,%3}, {%4,%5,%6,%7}, {%8,%9}, {%0,%1,%2,%3};" \
        : "+f"((c)[0]), "+f"((c)[1]), "+f"((c)[2]), "+f"((c)[3]) \
        : "r"(a0), "r"(a1), "r"(a2), "r"(a3), "r"(b0), "r"(b1))

static __device__ __forceinline__ float sigmoidf_(float x) {
    return 1.0f / (1.0f + __expf(-x));
}
static __device__ __forceinline__ float tanhf_(float x) {
    return 2.0f / (1.0f + __expf(-2.0f * x)) - 1.0f;
}

// ---------------- init ------------------------------------------------------
__global__ void init_state() {
    int i = blockIdx.x * blockDim.x + threadIdx.x;
    if (i < BATCH * 2048) g_hcat[0][i] = __float2bfloat16(0.0f);
    if (i == 0) { g_bar_count = 0u; g_bar_gen = 0u; }
}

// row r = 4j+g  <-  W_hh row g*HID + j ; cols: [hi(1024) | lo(1024)]
__global__ void wsplit(const float* __restrict__ W) {
    size_t idx = (size_t)blockIdx.x * 256 + threadIdx.x;
    if (idx >= (size_t)GATES * HID) return;
    int r = (int)(idx >> 10), k = (int)(idx & 1023);
    int j = r >> 2, g = r & 3;
    float v = W[(size_t)(g * HID + j) * HID + k];
    __nv_bfloat16 hi = __float2bfloat16(v);
    __nv_bfloat16 lo = __float2bfloat16(v - __bfloat162float(hi));
    __nv_bfloat16* o = g_w2 + (size_t)r * 2048;
    o[k] = hi; o[1024 + k] = lo;
}

// X[m][k] -> g_xs[m] = [Xhi | Xlo | Xhi]
__global__ void xsplit(const float* __restrict__ X) {
    size_t idx = (size_t)blockIdx.x * 256 + threadIdx.x;
    if (idx >= (size_t)BATCH * SEQ * DIN) return;
    int m = (int)(idx / DIN), k = (int)(idx % DIN);
    float v = X[idx];
    __nv_bfloat16 hi = __float2bfloat16(v);
    __nv_bfloat16 lo = __float2bfloat16(v - __bfloat162float(hi));
    __nv_bfloat16* o = g_xs + (size_t)m * KX;
    o[k] = hi; o[DIN + k] = lo; o[2 * DIN + k] = hi;
}

// W_ih[n][k] -> g_ws[n] = [Whi | Whi | Wlo]
__global__ void wihsplit(const float* __restrict__ W) {
    size_t idx = (size_t)blockIdx.x * 256 + threadIdx.x;
    if (idx >= (size_t)GATES * DIN) return;
    int n = (int)(idx / DIN), k = (int)(idx % DIN);
    float v = W[idx];
    __nv_bfloat16 hi = __float2bfloat16(v);
    __nv_bfloat16 lo = __float2bfloat16(v - __bfloat162float(hi));
    __nv_bfloat16* o = g_ws + (size_t)n * KX;
    o[k] = hi; o[DIN + k] = hi; o[2 * DIN + k] = lo;
}

// ---------------- Phase 1: x_proj HMMA GEMM --------------------------------
// C[32768 x 4096] = g_xs[32768 x 1632] * g_ws[4096 x 1632]^T  (K-major both)
// CTA tile 128x128, k-chunk 32, 8 warps (2x4), warp tile 64x32.
// smem rows padded to 80B => conflict-free ldmatrix (stride 80 mod 128 cycles).
__global__ __launch_bounds__(256) void xproj_hmma(
    const float* __restrict__ bih, const float* __restrict__ bhh)
{
    __shared__ __align__(128) char xsm[4 * 10240];   // A0,B0,A1,B1
    const uint32_t sb = smem_u32(xsm);
    const int tid = threadIdx.x, wid = tid >> 5, lane = tid & 31;
    const int n0 = blockIdx.x * 128, m0 = blockIdx.y * 128;
    const int wm = wid & 1, wn = wid >> 1;
    const int lrow = lane & 15, lk = lane >> 4;

    float c[4][4][4];
#pragma unroll
    for (int a = 0; a < 4; ++a)
#pragma unroll
        for (int b = 0; b < 4; ++b)
#pragma unroll
            for (int d = 0; d < 4; ++d) c[a][b][d] = 0.0f;

    auto loadAB = [&](int kc, int buf) {
        const int k0 = kc * 32;
        const uint32_t sA = sb + buf * 20480;
        const uint32_t sB = sA + 10240;
#pragma unroll
        for (int w = 0; w < 2; ++w) {
            int v = tid + 256 * w;          // 0..511
            int row = v >> 2, u = v & 3;
            cp16(sA + row * 80 + u * 16, g_xs + (size_t)(m0 + row) * KX + k0 + u * 8);
            cp16(sB + row * 80 + u * 16, g_ws + (size_t)(n0 + row) * KX + k0 + u * 8);
        }
        CP_COMMIT();
    };

    const int NKC = KX / 32;   // 51
    loadAB(0, 0);
    for (int kc = 0; kc < NKC; ++kc) {
        if (kc + 1 < NKC) { loadAB(kc + 1, (kc + 1) & 1); CP_WAIT1(); }
        else             { CP_WAIT0(); }
        __syncthreads();
        const uint32_t aBase = sb + (kc & 1) * 20480;
        const uint32_t bBase = aBase + 10240;
#pragma unroll
        for (int kt = 0; kt < 2; ++kt) {
            uint32_t A[4][4], Bq[2][4];
#pragma unroll
            for (int mt = 0; mt < 4; ++mt)
                LDSM4(A[mt][0], A[mt][1], A[mt][2], A[mt][3],
                      aBase + (64 * wm + 16 * mt + lrow) * 80 + kt * 32 + lk * 16);
#pragma unroll
            for (int ng = 0; ng < 2; ++ng)
                LDSM4(Bq[ng][0], Bq[ng][1], Bq[ng][2], Bq[ng][3],
                      bBase + (32 * wn + 16 * ng + lrow) * 80 + kt * 32 + lk * 16);
#pragma unroll
            for (int mt = 0; mt < 4; ++mt)
#pragma unroll
                for (int ng = 0; ng < 2; ++ng) {
                    MMA16816(c[mt][2 * ng],     A[mt][0], A[mt][1], A[mt][2], A[mt][3],
                             Bq[ng][0], Bq[ng][2]);
                    MMA16816(c[mt][2 * ng + 1], A[mt][0], A[mt][1], A[mt][2], A[mt][3],
                             Bq[ng][1], Bq[ng][3]);
                }
        }
        __syncthreads();
    }

    // epilogue: add bias, scatter to g_xproj[(s*64+b)*4096 + n]
    float2 bias[4];
#pragma unroll
    for (int nt = 0; nt < 4; ++nt) {
        int n = n0 + 32 * wn + 8 * nt + 2 * (lane & 3);
        bias[nt] = make_float2(bih[n] + bhh[n], bih[n + 1] + bhh[n + 1]);
    }
    const int r0 = m0 + 64 * wm + (lane >> 2);
#pragma unroll
    for (int mt = 0; mt < 4; ++mt) {
#pragma unroll
        for (int h = 0; h < 2; ++h) {
            int m = r0 + 16 * mt + 8 * h;
            int b = m >> 9, s = m & 511;
            float* orow = g_xproj + ((size_t)(s * BATCH + b)) * GATES;
#pragma unroll
            for (int nt = 0; nt < 4; ++nt) {
                int n = n0 + 32 * wn + 8 * nt + 2 * (lane & 3);
                *(float2*)(orow + n) = make_float2(c[mt][nt][2 * h] + bias[nt].x,
                                                   c[mt][nt][2 * h + 1] + bias[nt].y);
            }
        }
    }
}

// ---------------- Phase 2: persistent HMMA LSTM ----------------------------
#define SM_W    0
#define SM_RING 131072
#define SM_ST   180224
#define SM_CS   188544
#define SMEM_DYN 190592

__device__ __forceinline__ void grid_barrier(unsigned target) {
    __syncthreads();
    if (threadIdx.x == 0) {
        __threadfence();
        unsigned arr = atomicAdd(&g_bar_count, 1u);
        if (arr == NCTA - 1u) {
            g_bar_count = 0u;
            __threadfence();
            atomicAdd(&g_bar_gen, 1u);
        } else {
            unsigned g;
            do {
                asm volatile("ld.acquire.gpu.global.u32 %0, [%1];"
                             : "=r"(g) : "l"(&g_bar_gen));
            } while (g < target);
        }
        __threadfence();
    }
    __syncthreads();
}

__global__ __launch_bounds__(256, 1) void lstm_persistent(float* __restrict__ out) {
    extern __shared__ char smem[];
    const uint32_t sb = smem_u32(smem);
    const int tid = threadIdx.x, wid = tid >> 5, lane = tid & 31;
    const int rbase = blockIdx.x * 32;    // reordered W rows
    const int jbase = blockIdx.x * 8;     // hidden cols

    float (*st)[65] = (float (*)[65])(smem + SM_ST);
    float* cs = (float*)(smem + SM_CS);

    // ---- load W slice into smem once (128 KB) ----
#pragma unroll 8
    for (int w = 0; w < 32; ++w) {
        int v = tid + 256 * w;            // 0..8191
        int row = v >> 8, u = v & 255;
        int reg = u >> 7, uu = u & 127;
        uint32_t dst = sb + SM_W + reg * 65536 + row * 2048
                     + (((uu) & ~7) | ((uu ^ row) & 7)) * 16;
        cp16(dst, g_w2 + (size_t)(rbase + row) * 2048 + u * 8);
    }
    CP_COMMIT();
    cs[tid] = 0.0f; cs[tid + 256] = 0.0f;
    CP_WAIT0();
    __syncthreads();

    // per-warp invariants
    const int mi = wid & 1, ni = wid >> 1;
    const int lrow = lane & 15, lk = lane >> 4;
    const int arow = 16 * mi + lrow;
    const int brow = 16 * ni + lrow;
    const uint32_t aHi = sb + SM_W + arow * 2048;
    const uint32_t aLo = aHi + 65536;
    const uint32_t bRow0 = sb + SM_RING + brow * 256;

    // epilogue mapping
    const int ejl = tid & 7, emh = tid >> 3;

    for (int t = 0; t < SEQ; ++t) {
        const __nv_bfloat16* __restrict__ hin = g_hcat[t & 1];
        __nv_bfloat16* __restrict__ hout = g_hcat[(t & 1) ^ 1];
        const float* __restrict__ xp = g_xproj + (size_t)t * BATCH * GATES;

        // hoist xp gate loads (latency hidden under the MMA loop)
        const int ej = jbase + ejl;
        const float* xr0 = xp + (size_t)emh * GATES;
        const float* xr1 = xr0 + (size_t)32 * GATES;
        float xg0[4], xg1[4];
#pragma unroll
        for (int g = 0; g < 4; ++g) {
            xg0[g] = __ldg(xr0 + g * HID + ej);
            xg1[g] = __ldg(xr1 + g * HID + ej);
        }

        float ca[4] = {0.f, 0.f, 0.f, 0.f};
        float cb[4] = {0.f, 0.f, 0.f, 0.f};

        auto issue_h = [&](int jc) {
            const int q = jc >> 1;
            const int koff = ((jc & 1) ? 1024 : 0) + q * 128;
            const uint32_t dst0 = sb + SM_RING + (jc % 3) * 16384;
#pragma unroll
            for (int w = 0; w < 4; ++w) {
                int v = tid + 256 * w;        // 0..1023
                int n = v >> 4, u = v & 15;
                uint32_t dst = dst0 + n * 256 + ((u & ~7) | ((u ^ n) & 7)) * 16;
                cp16(dst, hin + (size_t)n * 2048 + koff + u * 8);
            }
            CP_COMMIT();
        };

        issue_h(0);
        issue_h(1);

#pragma unroll 1
        for (int q = 0; q < 8; ++q) {
            // wait hhi_q, issue next
            {
                const int li = 2 * q;
                if (li < 15) { CP_WAIT1(); } else { CP_WAIT0(); }
                __syncthreads();
                if (li + 2 <= 15) issue_h(li + 2);
            }
            const uint32_t bHiB = bRow0 + ((2 * q) % 3) * 16384;
            uint32_t Ah[8][4], Bh[8][4];
            // pass 1: Whi x hhi (cache A-hi and B-hi frags)
#pragma unroll
            for (int ks = 0; ks < 8; ++ks) {
                int ua = q * 16 + 2 * ks + lk;
                uint32_t aaddr = aHi + ((ua & ~7) | ((ua ^ arow) & 7)) * 16;
                int ub = 2 * ks + lk;
                uint32_t baddr = bHiB + ((ub & ~7) | ((ub ^ brow) & 7)) * 16;
                LDSM4(Ah[ks][0], Ah[ks][1], Ah[ks][2], Ah[ks][3], aaddr);
                LDSM4(Bh[ks][0], Bh[ks][1], Bh[ks][2], Bh[ks][3], baddr);
                MMA16816(ca, Ah[ks][0], Ah[ks][1], Ah[ks][2], Ah[ks][3], Bh[ks][0], Bh[ks][2]);
                MMA16816(cb, Ah[ks][0], Ah[ks][1], Ah[ks][2], Ah[ks][3], Bh[ks][1], Bh[ks][3]);
            }
            // pass 2: Wlo x hhi (reuse cached B-hi)
#pragma unroll
            for (int ks = 0; ks < 8; ++ks) {
                int ua = q * 16 + 2 * ks + lk;
                uint32_t aaddr = aLo + ((ua & ~7) | ((ua ^ arow) & 7)) * 16;
                uint32_t l0, l1, l2, l3;
                LDSM4(l0, l1, l2, l3, aaddr);
                MMA16816(ca, l0, l1, l2, l3, Bh[ks][0], Bh[ks][2]);
                MMA16816(cb, l0, l1, l2, l3, Bh[ks][1], Bh[ks][3]);
            }
            // wait hlo_q, issue next
            {
                const int li = 2 * q + 1;
                if (li < 15) { CP_WAIT1(); } else { CP_WAIT0(); }
                __syncthreads();
                if (li + 2 <= 15) issue_h(li + 2);
            }
            // pass 3: Whi x hlo (reuse cached A-hi)
            const uint32_t bLoB = bRow0 + ((2 * q + 1) % 3) * 16384;
#pragma unroll
            for (int ks = 0; ks < 8; ++ks) {
                int ub = 2 * ks + lk;
                uint32_t baddr = bLoB + ((ub & ~7) | ((ub ^ brow) & 7)) * 16;
                uint32_t l0, l1, l2, l3;
                LDSM4(l0, l1, l2, l3, baddr);
                MMA16816(ca, Ah[ks][0], Ah[ks][1], Ah[ks][2], Ah[ks][3], l0, l2);
                MMA16816(cb, Ah[ks][0], Ah[ks][1], Ah[ks][2], Ah[ks][3], l1, l3);
            }
        }

        // ---- stage C frags ----
        {
            const int gid = lane >> 2, tig = lane & 3;
            const int r0 = 16 * mi + gid;
            const int c0 = 16 * ni + 2 * tig;
            st[r0][c0]         = ca[0]; st[r0][c0 + 1]     = ca[1];
            st[r0 + 8][c0]     = ca[2]; st[r0 + 8][c0 + 1] = ca[3];
            st[r0][c0 + 8]     = cb[0]; st[r0][c0 + 9]     = cb[1];
            st[r0 + 8][c0 + 8] = cb[2]; st[r0 + 8][c0 + 9] = cb[3];
        }
        __syncthreads();

        // ---- fused LSTM elementwise epilogue ----
#pragma unroll
        for (int pass = 0; pass < 2; ++pass) {
            const int m = emh + pass * 32;
            const float* xg = pass ? xg1 : xg0;
            const int j = jbase + ejl;
            float gi = st[ejl * 4 + 0][m] + xg[0];
            float gf = st[ejl * 4 + 1][m] + xg[1];
            float gg = st[ejl * 4 + 2][m] + xg[2];
            float go = st[ejl * 4 + 3][m] + xg[3];
            float cold = cs[m * 8 + ejl];
            float cn = sigmoidf_(gf) * cold + sigmoidf_(gi) * tanhf_(gg);
            cs[m * 8 + ejl] = cn;
            float h = sigmoidf_(go) * tanhf_(cn);
            __nv_bfloat16 hi = __float2bfloat16(h);
            __nv_bfloat16 lo = __float2bfloat16(h - __bfloat162float(hi));
            hout[(size_t)m * 2048 + j] = hi;
            hout[(size_t)m * 2048 + 1024 + j] = lo;
            if (t == SEQ - 1) {
                out[(size_t)m * HID + j] = h;
                out[(size_t)BATCH * HID + (size_t)m * HID + j] = cn;
            }
        }

        if (t < SEQ - 1) grid_barrier((unsigned)(t + 1));
    }
}

// ---------------- launch ---------------------------------------------------
extern "C" void kernel_launch(void* const* d_in, const int* in_sizes, int n_in,
                              void* d_out, int out_size) {
    const float* X   = (const float*)d_in[0];
    const float* Wih = (const float*)d_in[1];
    const float* Whh = (const float*)d_in[2];
    const float* bih = (const float*)d_in[3];
    const float* bhh = (const float*)d_in[4];
    float* out = (float*)d_out;

    static int configured = 0;
    if (!configured) {
        cudaFuncSetAttribute(lstm_persistent,
                             cudaFuncAttributeMaxDynamicSharedMemorySize, SMEM_DYN);
        configured = 1;
    }

    init_state<<<512, 256>>>();
    wsplit<<<(GATES * HID) / 256, 256>>>(Whh);
    xsplit<<<(BATCH * SEQ * DIN) / 256, 256>>>(X);
    wihsplit<<<(GATES * DIN) / 256, 256>>>(Wih);
    xproj_hmma<<<dim3(GATES / 128, (BATCH * SEQ) / 128), 256>>>(bih, bhh);
    lstm_persistent<<<NCTA, 256, SMEM_DYN>>>(out);
}

// round 9
// speedup vs baseline: 4.4300x; 1.0365x over previous
#include <cuda_runtime.h>
#include <cuda_bf16.h>
#include <cstdint>

#define BATCH 64
#define SEQ   512
#define DIN   544
#define HID   1024
#define GATES 4096
#define NCTA  128
#define KX    1632   // 3*544 split-K for xproj

// ---------------- device-global scratch ------------------------------------
__device__ float          g_xproj[(size_t)SEQ * BATCH * GATES];   // [s][b][4H]
__device__ __nv_bfloat16  g_w2[(size_t)GATES * 2048];             // r=4j+g: [Whi|Wlo]
__device__ __nv_bfloat16  g_hcat[2][(size_t)BATCH * 2048];        // [m][hhi|hlo]
__device__ __nv_bfloat16  g_xs[(size_t)BATCH * SEQ * KX];         // [m][Xhi|Xlo|Xhi]
__device__ __nv_bfloat16  g_ws[(size_t)GATES * KX];               // [n][Whi|Whi|Wlo]
__device__ unsigned       g_bar_count;
__device__ unsigned       g_bar_gen;

// ---------------- helpers ---------------------------------------------------
static __device__ __forceinline__ uint32_t smem_u32(const void* p) {
    uint32_t a;
    asm("{ .reg .u64 t; cvta.to.shared.u64 t, %1; cvt.u32.u64 %0, t; }" : "=r"(a) : "l"(p));
    return a;
}
static __device__ __forceinline__ void cp16(uint32_t dst, const void* src) {
    asm volatile("cp.async.cg.shared.global [%0], [%1], 16;" :: "r"(dst), "l"(src) : "memory");
}
#define CP_COMMIT() asm volatile("cp.async.commit_group;" ::: "memory")
#define CP_WAIT1()  asm volatile("cp.async.wait_group 1;" ::: "memory")
#define CP_WAIT0()  asm volatile("cp.async.wait_group 0;" ::: "memory")

#define LDSM4(r0, r1, r2, r3, addr) \
    asm volatile("ldmatrix.sync.aligned.m8n8.x4.shared.b16 {%0,%1,%2,%3}, [%4];" \
        : "=r"(r0), "=r"(r1), "=r"(r2), "=r"(r3) : "r"(addr))

#define MMA16816(c, a0, a1, a2, a3, b0, b1) \
    asm volatile("mma.sync.aligned.m16n8k16.row.col.f32.bf16.bf16.f32 " \
        "{%0,%1,%2,%3}, {%4,%5,%6,%7}, {%8,%9}, {%0,%1,%2,%3};" \
        : "+f"((c)[0]), "+f"((c)[1]), "+f"((c)[2]), "+f"((c)[3]) \
        : "r"(a0), "r"(a1), "r"(a2), "r"(a3), "r"(b0), "r"(b1))

static __device__ __forceinline__ float sigmoidf_(float x) {
    return 1.0f / (1.0f + __expf(-x));
}
static __device__ __forceinline__ float tanhf_(float x) {
    return 2.0f / (1.0f + __expf(-2.0f * x)) - 1.0f;
}

// ---------------- init ------------------------------------------------------
__global__ void init_state() {
    int i = blockIdx.x * blockDim.x + threadIdx.x;
    if (i < BATCH * 2048) g_hcat[0][i] = __float2bfloat16(0.0f);
    if (i == 0) { g_bar_count = 0u; g_bar_gen = 0u; }
}

// row r = 4j+g  <-  W_hh row g*HID + j ; cols: [hi(1024) | lo(1024)]
__global__ void wsplit(const float* __restrict__ W) {
    size_t idx = (size_t)blockIdx.x * 256 + threadIdx.x;
    if (idx >= (size_t)GATES * HID) return;
    int r = (int)(idx >> 10), k = (int)(idx & 1023);
    int j = r >> 2, g = r & 3;
    float v = W[(size_t)(g * HID + j) * HID + k];
    __nv_bfloat16 hi = __float2bfloat16(v);
    __nv_bfloat16 lo = __float2bfloat16(v - __bfloat162float(hi));
    __nv_bfloat16* o = g_w2 + (size_t)r * 2048;
    o[k] = hi; o[1024 + k] = lo;
}

// X[m][k] -> g_xs[m] = [Xhi | Xlo | Xhi]
__global__ void xsplit(const float* __restrict__ X) {
    size_t idx = (size_t)blockIdx.x * 256 + threadIdx.x;
    if (idx >= (size_t)BATCH * SEQ * DIN) return;
    int m = (int)(idx / DIN), k = (int)(idx % DIN);
    float v = X[idx];
    __nv_bfloat16 hi = __float2bfloat16(v);
    __nv_bfloat16 lo = __float2bfloat16(v - __bfloat162float(hi));
    __nv_bfloat16* o = g_xs + (size_t)m * KX;
    o[k] = hi; o[DIN + k] = lo; o[2 * DIN + k] = hi;
}

// W_ih[n][k] -> g_ws[n] = [Whi | Whi | Wlo]
__global__ void wihsplit(const float* __restrict__ W) {
    size_t idx = (size_t)blockIdx.x * 256 + threadIdx.x;
    if (idx >= (size_t)GATES * DIN) return;
    int n = (int)(idx / DIN), k = (int)(idx % DIN);
    float v = W[idx];
    __nv_bfloat16 hi = __float2bfloat16(v);
    __nv_bfloat16 lo = __float2bfloat16(v - __bfloat162float(hi));
    __nv_bfloat16* o = g_ws + (size_t)n * KX;
    o[k] = hi; o[DIN + k] = hi; o[2 * DIN + k] = lo;
}

// ---------------- Phase 1: x_proj HMMA GEMM --------------------------------
__global__ __launch_bounds__(256) void xproj_hmma(
    const float* __restrict__ bih, const float* __restrict__ bhh)
{
    __shared__ __align__(128) char xsm[4 * 10240];   // A0,B0,A1,B1
    const uint32_t sb = smem_u32(xsm);
    const int tid = threadIdx.x, wid = tid >> 5, lane = tid & 31;
    const int n0 = blockIdx.x * 128, m0 = blockIdx.y * 128;
    const int wm = wid & 1, wn = wid >> 1;
    const int lrow = lane & 15, lk = lane >> 4;

    float c[4][4][4];
#pragma unroll
    for (int a = 0; a < 4; ++a)
#pragma unroll
        for (int b = 0; b < 4; ++b)
#pragma unroll
            for (int d = 0; d < 4; ++d) c[a][b][d] = 0.0f;

    auto loadAB = [&](int kc, int buf) {
        const int k0 = kc * 32;
        const uint32_t sA = sb + buf * 20480;
        const uint32_t sB = sA + 10240;
#pragma unroll
        for (int w = 0; w < 2; ++w) {
            int v = tid + 256 * w;
            int row = v >> 2, u = v & 3;
            cp16(sA + row * 80 + u * 16, g_xs + (size_t)(m0 + row) * KX + k0 + u * 8);
            cp16(sB + row * 80 + u * 16, g_ws + (size_t)(n0 + row) * KX + k0 + u * 8);
        }
        CP_COMMIT();
    };

    const int NKC = KX / 32;   // 51
    loadAB(0, 0);
    for (int kc = 0; kc < NKC; ++kc) {
        if (kc + 1 < NKC) { loadAB(kc + 1, (kc + 1) & 1); CP_WAIT1(); }
        else             { CP_WAIT0(); }
        __syncthreads();
        const uint32_t aBase = sb + (kc & 1) * 20480;
        const uint32_t bBase = aBase + 10240;
#pragma unroll
        for (int kt = 0; kt < 2; ++kt) {
            uint32_t A[4][4], Bq[2][4];
#pragma unroll
            for (int mt = 0; mt < 4; ++mt)
                LDSM4(A[mt][0], A[mt][1], A[mt][2], A[mt][3],
                      aBase + (64 * wm + 16 * mt + lrow) * 80 + kt * 32 + lk * 16);
#pragma unroll
            for (int ng = 0; ng < 2; ++ng)
                LDSM4(Bq[ng][0], Bq[ng][1], Bq[ng][2], Bq[ng][3],
                      bBase + (32 * wn + 16 * ng + lrow) * 80 + kt * 32 + lk * 16);
#pragma unroll
            for (int mt = 0; mt < 4; ++mt)
#pragma unroll
                for (int ng = 0; ng < 2; ++ng) {
                    MMA16816(c[mt][2 * ng],     A[mt][0], A[mt][1], A[mt][2], A[mt][3],
                             Bq[ng][0], Bq[ng][2]);
                    MMA16816(c[mt][2 * ng + 1], A[mt][0], A[mt][1], A[mt][2], A[mt][3],
                             Bq[ng][1], Bq[ng][3]);
                }
        }
        __syncthreads();
    }

    float2 bias[4];
#pragma unroll
    for (int nt = 0; nt < 4; ++nt) {
        int n = n0 + 32 * wn + 8 * nt + 2 * (lane & 3);
        bias[nt] = make_float2(bih[n] + bhh[n], bih[n + 1] + bhh[n + 1]);
    }
    const int r0 = m0 + 64 * wm + (lane >> 2);
#pragma unroll
    for (int mt = 0; mt < 4; ++mt) {
#pragma unroll
        for (int h = 0; h < 2; ++h) {
            int m = r0 + 16 * mt + 8 * h;
            int b = m >> 9, s = m & 511;
            float* orow = g_xproj + ((size_t)(s * BATCH + b)) * GATES;
#pragma unroll
            for (int nt = 0; nt < 4; ++nt) {
                int n = n0 + 32 * wn + 8 * nt + 2 * (lane & 3);
                *(float2*)(orow + n) = make_float2(c[mt][nt][2 * h] + bias[nt].x,
                                                   c[mt][nt][2 * h + 1] + bias[nt].y);
            }
        }
    }
}

// ---------------- Phase 2: persistent HMMA LSTM (512 thr, K-split 2) -------
// smem:
//   [0, 131072)        W slice: hi [32 rows x 2048B] at +0, lo at +65536
//   [131072, 196608)   h ring: 2 x 32768  (chunk q = 64 rows x [hhi 256B | hlo 256B])
//   [196608, 213248)   st[2][32][65] fp32 partial gate sums
//   [213248, 215296)   c slice [64 m][8 j]
#define SM_W    0
#define SM_RING 131072
#define SM_ST   196608
#define SM_CS   213248
#define SMEM_DYN 215296

__device__ __forceinline__ void grid_barrier(unsigned target) {
    __syncthreads();
    if (threadIdx.x == 0) {
        __threadfence();
        unsigned arr = atomicAdd(&g_bar_count, 1u);
        if (arr == NCTA - 1u) {
            g_bar_count = 0u;
            __threadfence();
            atomicAdd(&g_bar_gen, 1u);
        } else {
            unsigned g;
            do {
                asm volatile("ld.acquire.gpu.global.u32 %0, [%1];"
                             : "=r"(g) : "l"(&g_bar_gen));
            } while (g < target);
        }
        __threadfence();
    }
    __syncthreads();
}

__global__ __launch_bounds__(512, 1) void lstm_persistent(float* __restrict__ out) {
    extern __shared__ char smem[];
    const uint32_t sb = smem_u32(smem);
    const int tid = threadIdx.x, wid = tid >> 5, lane = tid & 31;
    const int rbase = blockIdx.x * 32;    // reordered W rows
    const int jbase = blockIdx.x * 8;     // hidden cols

    float (*st)[32][65] = (float (*)[32][65])(smem + SM_ST);
    float* cs = (float*)(smem + SM_CS);

    // ---- load W slice into smem once (128 KB) ----
#pragma unroll 8
    for (int w = 0; w < 16; ++w) {
        int v = tid + 512 * w;            // 0..8191
        int row = v >> 8, u = v & 255;
        int reg = u >> 7, uu = u & 127;
        uint32_t dst = sb + SM_W + reg * 65536 + row * 2048
                     + (((uu) & ~7) | ((uu ^ row) & 7)) * 16;
        cp16(dst, g_w2 + (size_t)(rbase + row) * 2048 + u * 8);
    }
    CP_COMMIT();
    cs[tid] = 0.0f;
    CP_WAIT0();
    __syncthreads();

    // warp decomposition: 16 warps = 2(M) x 4(N) x 2(Kg)
    const int mi = wid & 1, ni = (wid >> 1) & 3, kg = wid >> 3;
    const int lrow = lane & 15, lk = lane >> 4;
    const int arow = 16 * mi + lrow;
    const int brow = 16 * ni + lrow;
    const uint32_t aHi = sb + SM_W + arow * 2048;
    const uint32_t aLo = aHi + 65536;
    const uint32_t bRow0 = sb + SM_RING + brow * 512;

    // epilogue mapping: one (m, j) per thread
    const int ejl = tid & 7, em = tid >> 3;

    for (int t = 0; t < SEQ; ++t) {
        const __nv_bfloat16* __restrict__ hin = g_hcat[t & 1];
        __nv_bfloat16* __restrict__ hout = g_hcat[(t & 1) ^ 1];
        const float* __restrict__ xp = g_xproj + (size_t)t * BATCH * GATES;

        // hoist xp gate loads (hidden under MMA loop)
        const int ej = jbase + ejl;
        const float* xr = xp + (size_t)em * GATES;
        float xg[4];
#pragma unroll
        for (int g = 0; g < 4; ++g) xg[g] = __ldg(xr + g * HID + ej);

        float ca[4] = {0.f, 0.f, 0.f, 0.f};
        float cb[4] = {0.f, 0.f, 0.f, 0.f};

        // chunk q: 64 rows x [hhi(q) 128 cols | hlo(q) 128 cols]
        auto issue_h = [&](int q) {
            const uint32_t dst0 = sb + SM_RING + (q & 1) * 32768;
            const int koff = q * 128;
#pragma unroll
            for (int w = 0; w < 4; ++w) {
                int v = tid + 512 * w;        // 0..2047
                int n = v >> 5, u32 = v & 31;
                if (u32 < 16) {
                    uint32_t dst = dst0 + n * 512 + ((u32 & ~7) | ((u32 ^ n) & 7)) * 16;
                    cp16(dst, hin + (size_t)n * 2048 + koff + u32 * 8);
                } else {
                    int u = u32 - 16;
                    uint32_t dst = dst0 + n * 512 + 256 + ((u & ~7) | ((u ^ n) & 7)) * 16;
                    cp16(dst, hin + (size_t)n * 2048 + 1024 + koff + u * 8);
                }
            }
            CP_COMMIT();
        };

        issue_h(0);
        issue_h(1);

#pragma unroll 1
        for (int q = 0; q < 8; ++q) {
            if (q < 7) { CP_WAIT1(); } else { CP_WAIT0(); }
            __syncthreads();                        // chunk q visible
            const uint32_t bBase = bRow0 + (q & 1) * 32768;
            uint32_t Ah[4][4], Bh[4][4];
            // pass 1: Whi x hhi (cache A-hi and B-hi frags); warp's ks-half
#pragma unroll
            for (int ks = 0; ks < 4; ++ks) {
                int ua = q * 16 + 2 * (4 * kg + ks) + lk;
                uint32_t aaddr = aHi + ((ua & ~7) | ((ua ^ arow) & 7)) * 16;
                int ub = 2 * (4 * kg + ks) + lk;
                uint32_t baddr = bBase + ((ub & ~7) | ((ub ^ brow) & 7)) * 16;
                LDSM4(Ah[ks][0], Ah[ks][1], Ah[ks][2], Ah[ks][3], aaddr);
                LDSM4(Bh[ks][0], Bh[ks][1], Bh[ks][2], Bh[ks][3], baddr);
                MMA16816(ca, Ah[ks][0], Ah[ks][1], Ah[ks][2], Ah[ks][3], Bh[ks][0], Bh[ks][2]);
                MMA16816(cb, Ah[ks][0], Ah[ks][1], Ah[ks][2], Ah[ks][3], Bh[ks][1], Bh[ks][3]);
            }
            // pass 2: Wlo x hhi (reuse cached B-hi)
#pragma unroll
            for (int ks = 0; ks < 4; ++ks) {
                int ua = q * 16 + 2 * (4 * kg + ks) + lk;
                uint32_t aaddr = aLo + ((ua & ~7) | ((ua ^ arow) & 7)) * 16;
                uint32_t l0, l1, l2, l3;
                LDSM4(l0, l1, l2, l3, aaddr);
                MMA16816(ca, l0, l1, l2, l3, Bh[ks][0], Bh[ks][2]);
                MMA16816(cb, l0, l1, l2, l3, Bh[ks][1], Bh[ks][3]);
            }
            // pass 3: Whi x hlo (reuse cached A-hi)
#pragma unroll
            for (int ks = 0; ks < 4; ++ks) {
                int ub = 2 * (4 * kg + ks) + lk;
                uint32_t baddr = bBase + 256 + ((ub & ~7) | ((ub ^ brow) & 7)) * 16;
                uint32_t l0, l1, l2, l3;
                LDSM4(l0, l1, l2, l3, baddr);
                MMA16816(ca, Ah[ks][0], Ah[ks][1], Ah[ks][2], Ah[ks][3], l0, l2);
                MMA16816(cb, Ah[ks][0], Ah[ks][1], Ah[ks][2], Ah[ks][3], l1, l3);
            }
            __syncthreads();                        // all reads of buffer done
            if (q + 2 < 8) issue_h(q + 2);          // safe to overwrite
        }

        // ---- stage partial C frags (per kg) ----
        {
            const int gid = lane >> 2, tig = lane & 3;
            const int r0 = 16 * mi + gid;
            const int c0 = 16 * ni + 2 * tig;
            st[kg][r0][c0]         = ca[0]; st[kg][r0][c0 + 1]     = ca[1];
            st[kg][r0 + 8][c0]     = ca[2]; st[kg][r0 + 8][c0 + 1] = ca[3];
            st[kg][r0][c0 + 8]     = cb[0]; st[kg][r0][c0 + 9]     = cb[1];
            st[kg][r0 + 8][c0 + 8] = cb[2]; st[kg][r0 + 8][c0 + 9] = cb[3];
        }
        __syncthreads();

        // ---- fused LSTM elementwise epilogue (1 thread = 1 (m,j)) ----
        {
            const int m = em;
            const int j = jbase + ejl;
            float gi = st[0][ejl * 4 + 0][m] + st[1][ejl * 4 + 0][m] + xg[0];
            float gf = st[0][ejl * 4 + 1][m] + st[1][ejl * 4 + 1][m] + xg[1];
            float gg = st[0][ejl * 4 + 2][m] + st[1][ejl * 4 + 2][m] + xg[2];
            float go = st[0][ejl * 4 + 3][m] + st[1][ejl * 4 + 3][m] + xg[3];
            float cold = cs[m * 8 + ejl];
            float cn = sigmoidf_(gf) * cold + sigmoidf_(gi) * tanhf_(gg);
            cs[m * 8 + ejl] = cn;
            float h = sigmoidf_(go) * tanhf_(cn);
            __nv_bfloat16 hi = __float2bfloat16(h);
            __nv_bfloat16 lo = __float2bfloat16(h - __bfloat162float(hi));
            hout[(size_t)m * 2048 + j] = hi;
            hout[(size_t)m * 2048 + 1024 + j] = lo;
            if (t == SEQ - 1) {
                out[(size_t)m * HID + j] = h;
                out[(size_t)BATCH * HID + (size_t)m * HID + j] = cn;
            }
        }

        if (t < SEQ - 1) grid_barrier((unsigned)(t + 1));
    }
}

// ---------------- launch ---------------------------------------------------
extern "C" void kernel_launch(void* const* d_in, const int* in_sizes, int n_in,
                              void* d_out, int out_size) {
    const float* X   = (const float*)d_in[0];
    const float* Wih = (const float*)d_in[1];
    const float* Whh = (const float*)d_in[2];
    const float* bih = (const float*)d_in[3];
    const float* bhh = (const float*)d_in[4];
    float* out = (float*)d_out;

    static int configured = 0;
    if (!configured) {
        cudaFuncSetAttribute(lstm_persistent,
                             cudaFuncAttributeMaxDynamicSharedMemorySize, SMEM_DYN);
        configured = 1;
    }

    init_state<<<512, 256>>>();
    wsplit<<<(GATES * HID) / 256, 256>>>(Whh);
    xsplit<<<(BATCH * SEQ * DIN) / 256, 256>>>(X);
    wihsplit<<<(GATES * DIN) / 256, 256>>>(Wih);
    xproj_hmma<<<dim3(GATES / 128, (BATCH * SEQ) / 128), 256>>>(bih, bhh);
    lstm_persistent<<<NCTA, 512, SMEM_DYN>>>(out);
}

// round 10
// speedup vs baseline: 4.5180x; 1.0199x over previous
#include <cuda_runtime.h>
#include <cuda_bf16.h>
#include <cstdint>

#define BATCH 64
#define SEQ   512
#define DIN   544
#define HID   1024
#define GATES 4096
#define NCTA  128
#define KX    1632   // 3*544 split-K for xproj

// ---------------- device-global scratch ------------------------------------
__device__ float          g_xproj[(size_t)SEQ * BATCH * GATES];   // [s][b][4H]
// W slice per CTA: 131072 B contiguous, pre-swizzled for direct bulk->smem:
//   [reg(hi=0,lo=1)][row_local 0..31][128 units of 16B, XOR-swizzled by row]
__device__ __nv_bfloat16  g_w2[(size_t)NCTA * 65536];
// h, chunked+swizzled: [buf][chunk q 0..7][row m 0..63][512B: hi 16u | lo 16u]
__device__ __nv_bfloat16  g_hq[2][131072];
__device__ __nv_bfloat16  g_xs[(size_t)BATCH * SEQ * KX];         // [m][Xhi|Xlo|Xhi]
__device__ __nv_bfloat16  g_ws[(size_t)GATES * KX];               // [n][Whi|Whi|Wlo]
__device__ unsigned       g_bar_count;
__device__ unsigned       g_bar_gen;

// ---------------- helpers ---------------------------------------------------
static __device__ __forceinline__ uint32_t smem_u32(const void* p) {
    uint32_t a;
    asm("{ .reg .u64 t; cvta.to.shared.u64 t, %1; cvt.u32.u64 %0, t; }" : "=r"(a) : "l"(p));
    return a;
}
static __device__ __forceinline__ void cp16(uint32_t dst, const void* src) {
    asm volatile("cp.async.cg.shared.global [%0], [%1], 16;" :: "r"(dst), "l"(src) : "memory");
}
#define CP_COMMIT() asm volatile("cp.async.commit_group;" ::: "memory")
#define CP_WAIT1()  asm volatile("cp.async.wait_group 1;" ::: "memory")
#define CP_WAIT0()  asm volatile("cp.async.wait_group 0;" ::: "memory")

// bulk async copy: gmem -> smem, completes on mbarrier (UBLKCP)
static __device__ __forceinline__ void bulk_g2s(uint32_t dst, const void* src,
                                                uint32_t bytes, uint32_t mbar) {
    asm volatile(
        "cp.async.bulk.shared::cluster.global.mbarrier::complete_tx::bytes [%0], [%1], %2, [%3];"
        :: "r"(dst), "l"(src), "r"(bytes), "r"(mbar) : "memory");
}
#define MBAR_INIT(a, c) \
    asm volatile("mbarrier.init.shared.b64 [%0], %1;" :: "r"(a), "r"(c) : "memory")
#define MBAR_EXPECT(a, tx) \
    asm volatile("mbarrier.arrive.expect_tx.shared.b64 _, [%0], %1;" :: "r"(a), "r"(tx) : "memory")
#define MBAR_WAIT(a, p) do {                                                        \
    uint32_t _m = (a), _p = (p), _d;                                                \
    asm volatile("{\n\t.reg .pred q;\n\t"                                           \
        "mbarrier.try_wait.parity.acquire.cta.shared::cta.b64 q, [%1], %2;\n\t"     \
        "selp.b32 %0, 1, 0, q;\n\t}" : "=r"(_d) : "r"(_m), "r"(_p) : "memory");     \
    if (!_d) {                                                                      \
        asm volatile("{\n\t.reg .pred Q;\n\t"                                       \
            "W_%=:\n\t"                                                             \
            "mbarrier.try_wait.parity.acquire.cta.shared::cta.b64 Q, [%0], %1, 0x989680;\n\t" \
            "@Q bra.uni D_%=;\n\t"                                                  \
            "bra.uni W_%=;\n\t"                                                     \
            "D_%=:\n\t}" :: "r"(_m), "r"(_p) : "memory");                           \
    }                                                                               \
} while (0)

#define LDSM4(r0, r1, r2, r3, addr) \
    asm volatile("ldmatrix.sync.aligned.m8n8.x4.shared.b16 {%0,%1,%2,%3}, [%4];" \
        : "=r"(r0), "=r"(r1), "=r"(r2), "=r"(r3) : "r"(addr))

#define MMA16816(c, a0, a1, a2, a3, b0, b1) \
    asm volatile("mma.sync.aligned.m16n8k16.row.col.f32.bf16.bf16.f32 " \
        "{%0,%1,%2,%3}, {%4,%5,%6,%7}, {%8,%9}, {%0,%1,%2,%3};" \
        : "+f"((c)[0]), "+f"((c)[1]), "+f"((c)[2]), "+f"((c)[3]) \
        : "r"(a0), "r"(a1), "r"(a2), "r"(a3), "r"(b0), "r"(b1))

static __device__ __forceinline__ float sigmoidf_(float x) {
    return 1.0f / (1.0f + __expf(-x));
}
static __device__ __forceinline__ float tanhf_(float x) {
    return 2.0f / (1.0f + __expf(-2.0f * x)) - 1.0f;
}

// ---------------- init ------------------------------------------------------
__global__ void init_state() {
    int i = blockIdx.x * blockDim.x + threadIdx.x;
    if (i < 131072) g_hq[0][i] = __float2bfloat16(0.0f);
    if (i == 0) { g_bar_count = 0u; g_bar_gen = 0u; }
}

// W_hh row g*HID+j -> reordered row r=4j+g, CTA slice cta=r>>5, pre-swizzled.
__global__ void wsplit(const float* __restrict__ W) {
    size_t idx = (size_t)blockIdx.x * 256 + threadIdx.x;
    if (idx >= (size_t)GATES * HID) return;
    int r = (int)(idx >> 10), k = (int)(idx & 1023);
    int j = r >> 2, g = r & 3;
    float v = W[(size_t)(g * HID + j) * HID + k];
    __nv_bfloat16 hi = __float2bfloat16(v);
    __nv_bfloat16 lo = __float2bfloat16(v - __bfloat162float(hi));
    int cta = r >> 5, rl = r & 31;
    int uu = k >> 3;
    int sw = (uu & ~7) | ((uu ^ rl) & 7);
    __nv_bfloat16* o = g_w2 + (size_t)cta * 65536;
    size_t e = (size_t)rl * 1024 + sw * 8 + (k & 7);
    o[e] = hi;            // hi region
    o[32768 + e] = lo;    // lo region
}

// X[m][k] -> g_xs[m] = [Xhi | Xlo | Xhi]
__global__ void xsplit(const float* __restrict__ X) {
    size_t idx = (size_t)blockIdx.x * 256 + threadIdx.x;
    if (idx >= (size_t)BATCH * SEQ * DIN) return;
    int m = (int)(idx / DIN), k = (int)(idx % DIN);
    float v = X[idx];
    __nv_bfloat16 hi = __float2bfloat16(v);
    __nv_bfloat16 lo = __float2bfloat16(v - __bfloat162float(hi));
    __nv_bfloat16* o = g_xs + (size_t)m * KX;
    o[k] = hi; o[DIN + k] = lo; o[2 * DIN + k] = hi;
}

// W_ih[n][k] -> g_ws[n] = [Whi | Whi | Wlo]
__global__ void wihsplit(const float* __restrict__ W) {
    size_t idx = (size_t)blockIdx.x * 256 + threadIdx.x;
    if (idx >= (size_t)GATES * DIN) return;
    int n = (int)(idx / DIN), k = (int)(idx % DIN);
    float v = W[idx];
    __nv_bfloat16 hi = __float2bfloat16(v);
    __nv_bfloat16 lo = __float2bfloat16(v - __bfloat162float(hi));
    __nv_bfloat16* o = g_ws + (size_t)n * KX;
    o[k] = hi; o[DIN + k] = hi; o[2 * DIN + k] = lo;
}

// ---------------- Phase 1: x_proj HMMA GEMM (unchanged) --------------------
__global__ __launch_bounds__(256) void xproj_hmma(
    const float* __restrict__ bih, const float* __restrict__ bhh)
{
    __shared__ __align__(128) char xsm[4 * 10240];   // A0,B0,A1,B1
    const uint32_t sb = smem_u32(xsm);
    const int tid = threadIdx.x, wid = tid >> 5, lane = tid & 31;
    const int n0 = blockIdx.x * 128, m0 = blockIdx.y * 128;
    const int wm = wid & 1, wn = wid >> 1;
    const int lrow = lane & 15, lk = lane >> 4;

    float c[4][4][4];
#pragma unroll
    for (int a = 0; a < 4; ++a)
#pragma unroll
        for (int b = 0; b < 4; ++b)
#pragma unroll
            for (int d = 0; d < 4; ++d) c[a][b][d] = 0.0f;

    auto loadAB = [&](int kc, int buf) {
        const int k0 = kc * 32;
        const uint32_t sA = sb + buf * 20480;
        const uint32_t sB = sA + 10240;
#pragma unroll
        for (int w = 0; w < 2; ++w) {
            int v = tid + 256 * w;
            int row = v >> 2, u = v & 3;
            cp16(sA + row * 80 + u * 16, g_xs + (size_t)(m0 + row) * KX + k0 + u * 8);
            cp16(sB + row * 80 + u * 16, g_ws + (size_t)(n0 + row) * KX + k0 + u * 8);
        }
        CP_COMMIT();
    };

    const int NKC = KX / 32;   // 51
    loadAB(0, 0);
    for (int kc = 0; kc < NKC; ++kc) {
        if (kc + 1 < NKC) { loadAB(kc + 1, (kc + 1) & 1); CP_WAIT1(); }
        else             { CP_WAIT0(); }
        __syncthreads();
        const uint32_t aBase = sb + (kc & 1) * 20480;
        const uint32_t bBase = aBase + 10240;
#pragma unroll
        for (int kt = 0; kt < 2; ++kt) {
            uint32_t A[4][4], Bq[2][4];
#pragma unroll
            for (int mt = 0; mt < 4; ++mt)
                LDSM4(A[mt][0], A[mt][1], A[mt][2], A[mt][3],
                      aBase + (64 * wm + 16 * mt + lrow) * 80 + kt * 32 + lk * 16);
#pragma unroll
            for (int ng = 0; ng < 2; ++ng)
                LDSM4(Bq[ng][0], Bq[ng][1], Bq[ng][2], Bq[ng][3],
                      bBase + (32 * wn + 16 * ng + lrow) * 80 + kt * 32 + lk * 16);
#pragma unroll
            for (int mt = 0; mt < 4; ++mt)
#pragma unroll
                for (int ng = 0; ng < 2; ++ng) {
                    MMA16816(c[mt][2 * ng],     A[mt][0], A[mt][1], A[mt][2], A[mt][3],
                             Bq[ng][0], Bq[ng][2]);
                    MMA16816(c[mt][2 * ng + 1], A[mt][0], A[mt][1], A[mt][2], A[mt][3],
                             Bq[ng][1], Bq[ng][3]);
                }
        }
        __syncthreads();
    }

    float2 bias[4];
#pragma unroll
    for (int nt = 0; nt < 4; ++nt) {
        int n = n0 + 32 * wn + 8 * nt + 2 * (lane & 3);
        bias[nt] = make_float2(bih[n] + bhh[n], bih[n + 1] + bhh[n + 1]);
    }
    const int r0 = m0 + 64 * wm + (lane >> 2);
#pragma unroll
    for (int mt = 0; mt < 4; ++mt) {
#pragma unroll
        for (int h = 0; h < 2; ++h) {
            int m = r0 + 16 * mt + 8 * h;
            int b = m >> 9, s = m & 511;
            float* orow = g_xproj + ((size_t)(s * BATCH + b)) * GATES;
#pragma unroll
            for (int nt = 0; nt < 4; ++nt) {
                int n = n0 + 32 * wn + 8 * nt + 2 * (lane & 3);
                *(float2*)(orow + n) = make_float2(c[mt][nt][2 * h] + bias[nt].x,
                                                   c[mt][nt][2 * h + 1] + bias[nt].y);
            }
        }
    }
}

// ---------------- Phase 2: persistent HMMA LSTM (bulk-async loads) ---------
// smem:
//   [0, 131072)        W slice (hi at +0, lo at +65536), bulk-loaded once
//   [131072, 196608)   h ring: 2 x 32768 (chunk = 64 rows x [hi 256B | lo 256B])
//   [196608, 213248)   st[2][32][65] fp32 partial gate sums
//   [213248, 215296)   c slice [64 m][8 j]
//   [215296, 215360)   mbarriers: W, ring0, ring1
#define SM_W    0
#define SM_RING 131072
#define SM_ST   196608
#define SM_CS   213248
#define SM_MB   215296
#define SMEM_DYN 215360

__device__ __forceinline__ void grid_barrier(unsigned target) {
    __syncthreads();
    if (threadIdx.x == 0) {
        __threadfence();
        unsigned arr = atomicAdd(&g_bar_count, 1u);
        if (arr == NCTA - 1u) {
            g_bar_count = 0u;
            __threadfence();
            atomicAdd(&g_bar_gen, 1u);
        } else {
            unsigned g;
            do {
                asm volatile("ld.acquire.gpu.global.u32 %0, [%1];"
                             : "=r"(g) : "l"(&g_bar_gen));
            } while (g < target);
        }
        __threadfence();
    }
    __syncthreads();
}

__global__ __launch_bounds__(512, 1) void lstm_persistent(float* __restrict__ out) {
    extern __shared__ char smem[];
    const uint32_t sb = smem_u32(smem);
    const int tid = threadIdx.x, wid = tid >> 5, lane = tid & 31;
    const int jbase = blockIdx.x * 8;     // hidden cols

    float (*st)[32][65] = (float (*)[32][65])(smem + SM_ST);
    float* cs = (float*)(smem + SM_CS);
    const uint32_t mbW  = sb + SM_MB;
    const uint32_t mbR0 = sb + SM_MB + 8;

    // ---- init mbarriers, bulk-load W slice (128 KB, one op) ----
    if (tid == 0) {
        MBAR_INIT(mbW, 1);
        MBAR_INIT(mbR0, 1);
        MBAR_INIT(mbR0 + 8, 1);
    }
    __syncthreads();
    if (tid == 0) {
        MBAR_EXPECT(mbW, 131072u);
        bulk_g2s(sb + SM_W, g_w2 + (size_t)blockIdx.x * 65536, 131072u, mbW);
    }
    cs[tid] = 0.0f;
    MBAR_WAIT(mbW, 0u);
    __syncthreads();

    // warp decomposition: 16 warps = 2(M) x 4(N) x 2(Kg)
    const int mi = wid & 1, ni = (wid >> 1) & 3, kg = wid >> 3;
    const int lrow = lane & 15, lk = lane >> 4;
    const int arow = 16 * mi + lrow;
    const int brow = 16 * ni + lrow;
    const uint32_t aHi = sb + SM_W + arow * 2048;
    const uint32_t aLo = aHi + 65536;
    const uint32_t bRow0 = sb + SM_RING + brow * 512;

    // epilogue mapping: one (m, j) per thread
    const int ejl = tid & 7, em = tid >> 3;
    const int eq = jbase >> 7;                 // h chunk this CTA writes
    const int ej7 = (jbase & 127) + ejl;       // col within chunk
    const int eu = ej7 >> 3;
    const int esw = (eu & ~7) | ((eu ^ em) & 7);
    const size_t ebase = (size_t)eq * 16384 + (size_t)em * 256;

    unsigned pcnt[2] = {0u, 0u};               // ring-buffer completion counters

    for (int t = 0; t < SEQ; ++t) {
        const __nv_bfloat16* __restrict__ hin = g_hq[t & 1];
        __nv_bfloat16* __restrict__ hq = g_hq[(t & 1) ^ 1];
        const float* __restrict__ xp = g_xproj + (size_t)t * BATCH * GATES;

        // hoist xp gate loads (hidden under MMA loop)
        const int ej = jbase + ejl;
        const float* xr = xp + (size_t)em * GATES;
        float xg[4];
#pragma unroll
        for (int g = 0; g < 4; ++g) xg[g] = __ldg(xr + g * HID + ej);

        float ca[4] = {0.f, 0.f, 0.f, 0.f};
        float cb[4] = {0.f, 0.f, 0.f, 0.f};

        auto issue_chunk = [&](int q) {
            if (tid == 0) {
                uint32_t mb = mbR0 + (q & 1) * 8;
                MBAR_EXPECT(mb, 32768u);
                bulk_g2s(sb + SM_RING + (q & 1) * 32768, hin + (size_t)q * 16384,
                         32768u, mb);
            }
        };

        issue_chunk(0);
        issue_chunk(1);

#pragma unroll 1
        for (int q = 0; q < 8; ++q) {
            const int buf = q & 1;
            MBAR_WAIT(mbR0 + buf * 8, pcnt[buf] & 1u);
            pcnt[buf]++;
            const uint32_t bBase = bRow0 + buf * 32768;
            uint32_t Ah[4][4], Bh[4][4];
            // pass 1: Whi x hhi (cache A-hi and B-hi frags); warp's ks-half
#pragma unroll
            for (int ks = 0; ks < 4; ++ks) {
                int ua = q * 16 + 2 * (4 * kg + ks) + lk;
                uint32_t aaddr = aHi + ((ua & ~7) | ((ua ^ arow) & 7)) * 16;
                int ub = 2 * (4 * kg + ks) + lk;
                uint32_t baddr = bBase + ((ub & ~7) | ((ub ^ brow) & 7)) * 16;
                LDSM4(Ah[ks][0], Ah[ks][1], Ah[ks][2], Ah[ks][3], aaddr);
                LDSM4(Bh[ks][0], Bh[ks][1], Bh[ks][2], Bh[ks][3], baddr);
                MMA16816(ca, Ah[ks][0], Ah[ks][1], Ah[ks][2], Ah[ks][3], Bh[ks][0], Bh[ks][2]);
                MMA16816(cb, Ah[ks][0], Ah[ks][1], Ah[ks][2], Ah[ks][3], Bh[ks][1], Bh[ks][3]);
            }
            // pass 2: Wlo x hhi (reuse cached B-hi)
#pragma unroll
            for (int ks = 0; ks < 4; ++ks) {
                int ua = q * 16 + 2 * (4 * kg + ks) + lk;
                uint32_t aaddr = aLo + ((ua & ~7) | ((ua ^ arow) & 7)) * 16;
                uint32_t l0, l1, l2, l3;
                LDSM4(l0, l1, l2, l3, aaddr);
                MMA16816(ca, l0, l1, l2, l3, Bh[ks][0], Bh[ks][2]);
                MMA16816(cb, l0, l1, l2, l3, Bh[ks][1], Bh[ks][3]);
            }
            // pass 3: Whi x hlo (reuse cached A-hi)
#pragma unroll
            for (int ks = 0; ks < 4; ++ks) {
                int ub = 2 * (4 * kg + ks) + lk;
                uint32_t baddr = bBase + 256 + ((ub & ~7) | ((ub ^ brow) & 7)) * 16;
                uint32_t l0, l1, l2, l3;
                LDSM4(l0, l1, l2, l3, baddr);
                MMA16816(ca, Ah[ks][0], Ah[ks][1], Ah[ks][2], Ah[ks][3], l0, l2);
                MMA16816(cb, Ah[ks][0], Ah[ks][1], Ah[ks][2], Ah[ks][3], l1, l3);
            }
            __syncthreads();                        // all reads of buffer done
            if (q + 2 < 8) issue_chunk(q + 2);      // safe to overwrite
        }

        // ---- stage partial C frags (per kg) ----
        {
            const int gid = lane >> 2, tig = lane & 3;
            const int r0 = 16 * mi + gid;
            const int c0 = 16 * ni + 2 * tig;
            st[kg][r0][c0]         = ca[0]; st[kg][r0][c0 + 1]     = ca[1];
            st[kg][r0 + 8][c0]     = ca[2]; st[kg][r0 + 8][c0 + 1] = ca[3];
            st[kg][r0][c0 + 8]     = cb[0]; st[kg][r0][c0 + 9]     = cb[1];
            st[kg][r0 + 8][c0 + 8] = cb[2]; st[kg][r0 + 8][c0 + 9] = cb[3];
        }
        __syncthreads();

        // ---- fused LSTM elementwise epilogue (1 thread = 1 (m,j)) ----
        {
            const int m = em;
            const int j = jbase + ejl;
            float gi = st[0][ejl * 4 + 0][m] + st[1][ejl * 4 + 0][m] + xg[0];
            float gf = st[0][ejl * 4 + 1][m] + st[1][ejl * 4 + 1][m] + xg[1];
            float gg = st[0][ejl * 4 + 2][m] + st[1][ejl * 4 + 2][m] + xg[2];
            float go = st[0][ejl * 4 + 3][m] + st[1][ejl * 4 + 3][m] + xg[3];
            float cold = cs[m * 8 + ejl];
            float cn = sigmoidf_(gf) * cold + sigmoidf_(gi) * tanhf_(gg);
            cs[m * 8 + ejl] = cn;
            float h = sigmoidf_(go) * tanhf_(cn);
            __nv_bfloat16 hi = __float2bfloat16(h);
            __nv_bfloat16 lo = __float2bfloat16(h - __bfloat162float(hi));
            hq[ebase + esw * 8 + (ej7 & 7)] = hi;          // hi half (swizzled)
            hq[ebase + 128 + esw * 8 + (ej7 & 7)] = lo;    // lo half (swizzled)
            if (t == SEQ - 1) {
                out[(size_t)m * HID + j] = h;
                out[(size_t)BATCH * HID + (size_t)m * HID + j] = cn;
            }
        }

        if (t < SEQ - 1) grid_barrier((unsigned)(t + 1));
    }
}

// ---------------- launch ---------------------------------------------------
extern "C" void kernel_launch(void* const* d_in, const int* in_sizes, int n_in,
                              void* d_out, int out_size) {
    const float* X   = (const float*)d_in[0];
    const float* Wih = (const float*)d_in[1];
    const float* Whh = (const float*)d_in[2];
    const float* bih = (const float*)d_in[3];
    const float* bhh = (const float*)d_in[4];
    float* out = (float*)d_out;

    static int configured = 0;
    if (!configured) {
        cudaFuncSetAttribute(lstm_persistent,
                             cudaFuncAttributeMaxDynamicSharedMemorySize, SMEM_DYN);
        configured = 1;
    }

    init_state<<<512, 256>>>();
    wsplit<<<(GATES * HID) / 256, 256>>>(Whh);
    xsplit<<<(BATCH * SEQ * DIN) / 256, 256>>>(X);
    wihsplit<<<(GATES * DIN) / 256, 256>>>(Wih);
    xproj_hmma<<<dim3(GATES / 128, (BATCH * SEQ) / 128), 256>>>(bih, bhh);
    lstm_persistent<<<NCTA, 512, SMEM_DYN>>>(out);
}